// round 11
// baseline (speedup 1.0000x reference)
#include <cuda_runtime.h>
#include <cuda_fp16.h>
#include <cstdint>

#define BATCH 8
#define EDGES 16384
#define C0 128
#define C1 256
#define OUTC 256
#define KD0 (6 * C0)   // 768  (x5 column folded into weights)
#define KD1 (6 * C1)   // 1536
#define NEG 0.01f
#define BN_EPS_ 1e-5f

// ---------------- static device scratch ----------------
__device__ __half g_Ahf[(size_t)BATCH * EDGES * 2 * KD1];  // [M][hi(K)|lo(K)] fp16
__device__ __half g_W0h[OUTC * KD0];                       // [o][K] single fp16
__device__ __half g_W1h[OUTC * KD1];
__device__ float g_xt[(size_t)BATCH * EDGES * C0];
__device__ float g_at[(size_t)BATCH * EDGES * C1];   // lrelu(h0) transposed (pre-BN)
__device__ float g_h0[(size_t)BATCH * OUTC * EDGES];
__device__ float g_sum1[OUTC], g_sum2[OUTC], g_scale[OUTC], g_shift[OUTC];

// ---------------- helpers ----------------
__device__ __forceinline__ uint32_t smem_u32(const void* p) {
    uint32_t a;
    asm("{ .reg .u64 t; cvta.to.shared.u64 t, %1; cvt.u32.u64 %0, t; }" : "=r"(a) : "l"(p));
    return a;
}
__device__ __forceinline__ uint32_t sw64(uint32_t x) { return x ^ ((x >> 3) & 0x30); }
__device__ __forceinline__ void cpa16(uint32_t s, const void* g) {
    asm volatile("cp.async.cg.shared.global [%0], [%1], 16;" :: "r"(s), "l"(g));
}
__device__ __forceinline__ void cpa_commit() { asm volatile("cp.async.commit_group;"); }
__device__ __forceinline__ void cpa_wait2() { asm volatile("cp.async.wait_group 2;"); }

__device__ __forceinline__ void ldsm4(uint32_t* r, uint32_t addr) {
    asm volatile("ldmatrix.sync.aligned.m8n8.x4.shared.b16 {%0,%1,%2,%3}, [%4];"
                 : "=r"(r[0]), "=r"(r[1]), "=r"(r[2]), "=r"(r[3]) : "r"(addr));
}
__device__ __forceinline__ void mma16816(float* d, const uint32_t* a, uint32_t b0, uint32_t b1) {
    asm volatile(
        "mma.sync.aligned.m16n8k16.row.col.f32.f16.f16.f32 "
        "{%0,%1,%2,%3}, {%4,%5,%6,%7}, {%8,%9}, {%0,%1,%2,%3};"
        : "+f"(d[0]), "+f"(d[1]), "+f"(d[2]), "+f"(d[3])
        : "r"(a[0]), "r"(a[1]), "r"(a[2]), "r"(a[3]), "r"(b0), "r"(b1));
}

// ---------------- W prep: fold x5 col into x1,x2; drop x5. [o][K6] single fp16 ----------------
// feature order per channel: 0:f0 1:x1 2:x2 3:x3 4:x4 5:x6
template <int WHICH>
__global__ void prep_wh(const float* __restrict__ W) {
    constexpr int C = (WHICH == 0) ? C0 : C1;
    constexpr int K6 = 6 * C;
    __half* Wh = (WHICH == 0) ? g_W0h : g_W1h;
    if (WHICH == 0 && blockIdx.x == 0 && threadIdx.x < 256) {
        g_sum1[threadIdx.x] = 0.f;
        g_sum2[threadIdx.x] = 0.f;
    }
    int i = blockIdx.x * blockDim.x + threadIdx.x;
    if (i < OUTC * K6) {
        int kp = i % K6, o = i / K6;
        int c = kp / 6, jp = kp % 6;
        int jorig = (jp == 5) ? 6 : jp;
        float v = W[(size_t)o * (7 * C) + c * 7 + jorig];
        if (jp == 1 || jp == 2) v += W[(size_t)o * (7 * C) + c * 7 + 5];  // fold x5
        Wh[(size_t)o * K6 + kp] = __float2half(v);
    }
}

// ---------------- transpose x [B][C0][E] -> g_xt [B][E][C0] ----------------
__global__ void transpose_x(const float* __restrict__ x) {
    __shared__ float tile[32][33];
    int b = blockIdx.z;
    int e0 = blockIdx.x * 32, c0 = blockIdx.y * 32;
    int tx = threadIdx.x, ty = threadIdx.y;
#pragma unroll
    for (int i = 0; i < 32; i += 8)
        tile[ty + i][tx] = x[((size_t)b * C0 + (c0 + ty + i)) * EDGES + e0 + tx];
    __syncthreads();
#pragma unroll
    for (int i = 0; i < 32; i += 8)
        g_xt[((size_t)b * EDGES + (e0 + ty + i)) * C0 + c0 + tx] = tile[tx][ty + i];
}

// ---------------- gather + 6-feature build + fp16 hi/lo split ----------------
template <int STAGE>
__global__ __launch_bounds__(256, 1) void gather_hf(const int* __restrict__ gem) {
    constexpr int C = (STAGE == 0) ? C0 : C1;
    constexpr int K = 6 * C;
    constexpr int PITCH = 2 * K;
    constexpr int GPE = C / 8;
    const float* __restrict__ src = (STAGE == 0) ? g_xt : g_at;

    int gidx = blockIdx.x * blockDim.x + threadIdx.x;
    int m = gidx / GPE;
    int c = (gidx % GPE) * 8;
    size_t bE = (size_t)(m / EDGES) * EDGES;
    const int* gp = gem + (size_t)m * 4;
    int n0 = gp[0], n1 = gp[1], n2 = gp[2], n3 = gp[3];

    const float4* p0 = (const float4*)(src + (size_t)m * C + c);
    const float4* p1 = (const float4*)(src + (bE + n0) * (size_t)C + c);
    const float4* p2 = (const float4*)(src + (bE + n1) * (size_t)C + c);
    const float4* p3 = (const float4*)(src + (bE + n2) * (size_t)C + c);
    const float4* p4 = (const float4*)(src + (bE + n3) * (size_t)C + c);

    float f0[8], f1[8], f2[8], f3[8], f4[8];
    {
        float4 a = p0[0], b = p0[1];
        f0[0]=a.x; f0[1]=a.y; f0[2]=a.z; f0[3]=a.w; f0[4]=b.x; f0[5]=b.y; f0[6]=b.z; f0[7]=b.w;
        a = p1[0]; b = p1[1];
        f1[0]=a.x; f1[1]=a.y; f1[2]=a.z; f1[3]=a.w; f1[4]=b.x; f1[5]=b.y; f1[6]=b.z; f1[7]=b.w;
        a = p2[0]; b = p2[1];
        f2[0]=a.x; f2[1]=a.y; f2[2]=a.z; f2[3]=a.w; f2[4]=b.x; f2[5]=b.y; f2[6]=b.z; f2[7]=b.w;
        a = p3[0]; b = p3[1];
        f3[0]=a.x; f3[1]=a.y; f3[2]=a.z; f3[3]=a.w; f3[4]=b.x; f3[5]=b.y; f3[6]=b.z; f3[7]=b.w;
        a = p4[0]; b = p4[1];
        f4[0]=a.x; f4[1]=a.y; f4[2]=a.z; f4[3]=a.w; f4[4]=b.x; f4[5]=b.y; f4[6]=b.z; f4[7]=b.w;
    }

    if (STAGE == 1) {
        float4 s0 = *(const float4*)(g_scale + c), s1v = *(const float4*)(g_scale + c + 4);
        float4 h0 = *(const float4*)(g_shift + c), h1v = *(const float4*)(g_shift + c + 4);
        float sc[8] = {s0.x, s0.y, s0.z, s0.w, s1v.x, s1v.y, s1v.z, s1v.w};
        float sh[8] = {h0.x, h0.y, h0.z, h0.w, h1v.x, h1v.y, h1v.z, h1v.w};
#pragma unroll
        for (int k = 0; k < 8; k++) {
            f0[k] = fmaf(sc[k], f0[k], sh[k]);
            f1[k] = fmaf(sc[k], f1[k], sh[k]);
            f2[k] = fmaf(sc[k], f2[k], sh[k]);
            f3[k] = fmaf(sc[k], f3[k], sh[k]);
            f4[k] = fmaf(sc[k], f4[k], sh[k]);
        }
    }

    float feat[48];
#pragma unroll
    for (int cl = 0; cl < 8; cl++) {
        float a = f1[cl], b = f2[cl], cc = f3[cl], d = f4[cl];
        float x1 = a + cc, x2 = b + d, x5 = x1 + x2, avg = 0.25f * x5;
        float d1 = a - avg, d2 = b - avg, d3 = cc - avg, d4 = d - avg;
        feat[cl * 6 + 0] = f0[cl];
        feat[cl * 6 + 1] = x1;
        feat[cl * 6 + 2] = x2;
        feat[cl * 6 + 3] = fabsf(a - cc);
        feat[cl * 6 + 4] = fabsf(b - d);
        feat[cl * 6 + 5] = d1 * d1 + d2 * d2 + d3 * d3 + d4 * d4;
    }

    uint32_t hw[24], lw[24];
#pragma unroll
    for (int q = 0; q < 24; q++) {
        float v0 = feat[2 * q], v1 = feat[2 * q + 1];
        __half h0 = __float2half(v0), h1 = __float2half(v1);
        float l0 = v0 - __half2float(h0), l1 = v1 - __half2float(h1);
        __half g0 = __float2half(l0), g1 = __float2half(l1);
        hw[q] = (uint32_t)__half_as_ushort(h0) | ((uint32_t)__half_as_ushort(h1) << 16);
        lw[q] = (uint32_t)__half_as_ushort(g0) | ((uint32_t)__half_as_ushort(g1) << 16);
    }
    uint4* dh = (uint4*)(g_Ahf + (size_t)m * PITCH + c * 6);
    uint4* dl = (uint4*)(g_Ahf + (size_t)m * PITCH + K + c * 6);
#pragma unroll
    for (int q = 0; q < 6; q++) {
        dh[q] = make_uint4(hw[4 * q], hw[4 * q + 1], hw[4 * q + 2], hw[4 * q + 3]);
        dl[q] = make_uint4(lw[4 * q], lw[4 * q + 1], lw[4 * q + 2], lw[4 * q + 3]);
    }
}

// ---------------- mma.sync GEMM: D[128,256] per CTA, fp16 2-term split ----------------
#define AH_OFF 0
#define AL_OFF 8192
#define WH_OFF 16384
#define STG 32768
#define GEMM_SMEM 135168  // max(4 stages = 128KB, epilogue 256*129*4 + 2KB = 131KB)

template <int MODE>
__global__ __launch_bounds__(512, 1) void gemm_mma(float* __restrict__ outp) {
    constexpr int K = MODE ? KD1 : KD0;
    constexpr int T = K / 32;
    constexpr int PITCH = 2 * K;
    const __half* __restrict__ Wh = MODE ? g_W1h : g_W0h;

    extern __shared__ __align__(1024) char smem[];
    uint32_t sb = smem_u32(smem);
    const int tid = threadIdx.x, wid = tid >> 5, lane = tid & 31;
    const int wm = wid & 3, wn = wid >> 2;
    const size_t m0 = (size_t)blockIdx.x * 128;

    float acc[2][8][4];
#pragma unroll
    for (int i = 0; i < 2; i++)
#pragma unroll
        for (int j = 0; j < 8; j++)
#pragma unroll
            for (int k = 0; k < 4; k++) acc[i][j][k] = 0.f;

    const int lr = tid >> 2;   // 0..127
    const int lc = tid & 3;    // 16B chunk within 64B row
    const uint32_t adst = sw64(lr * 64 + lc * 16);

    auto load_stage = [&](int slot, int t) {
        const __half* Ag = g_Ahf + m0 * (size_t)PITCH + t * 32;
        const __half* Wg = Wh + t * 32;
        uint32_t st = sb + slot * STG;
        const __half* as = Ag + (size_t)lr * PITCH + lc * 8;
        cpa16(st + AH_OFF + adst, as);
        cpa16(st + AL_OFF + adst, as + K);
#pragma unroll
        for (int i = 0; i < 2; i++) {
            int r = lr + i * 128;
            const __half* ws = Wg + (size_t)r * K + lc * 8;
            cpa16(st + WH_OFF + sw64(r * 64 + lc * 16), ws);
        }
    };

    load_stage(0, 0); cpa_commit();
    load_stage(1, 1); cpa_commit();
    load_stage(2, 2); cpa_commit();

    const int lrow = lane & 15;
    const int lcol = (lane >> 4) * 16;

    for (int t = 0; t < T; t++) {
        int s = t & 3;
        cpa_wait2();
        __syncthreads();
        if (t + 3 < T) load_stage((t + 3) & 3, t + 3);
        cpa_commit();
        uint32_t st = sb + s * STG;
#pragma unroll
        for (int ks = 0; ks < 2; ks++) {
            int ko = ks * 32;
            uint32_t ah[2][4], al[2][4], bb[4][4];
#pragma unroll
            for (int mi = 0; mi < 2; mi++) {
                uint32_t ao = sw64((wm * 32 + mi * 16 + lrow) * 64 + ko + lcol);
                ldsm4(ah[mi], st + AH_OFF + ao);
                ldsm4(al[mi], st + AL_OFF + ao);
            }
#pragma unroll
            for (int nj = 0; nj < 4; nj++)
                ldsm4(bb[nj], st + WH_OFF + sw64((wn * 64 + nj * 16 + lrow) * 64 + ko + lcol));
            // pass 1: ah . wh
#pragma unroll
            for (int mi = 0; mi < 2; mi++)
#pragma unroll
                for (int nj = 0; nj < 4; nj++) {
                    mma16816(acc[mi][2 * nj], ah[mi], bb[nj][0], bb[nj][2]);
                    mma16816(acc[mi][2 * nj + 1], ah[mi], bb[nj][1], bb[nj][3]);
                }
            // pass 2: al . wh
#pragma unroll
            for (int mi = 0; mi < 2; mi++)
#pragma unroll
                for (int nj = 0; nj < 4; nj++) {
                    mma16816(acc[mi][2 * nj], al[mi], bb[nj][0], bb[nj][2]);
                    mma16816(acc[mi][2 * nj + 1], al[mi], bb[nj][1], bb[nj][3]);
                }
        }
    }

    // ---------------- epilogue: CTA transpose buffer ----------------
    __syncthreads();
    float* buf = (float*)smem;                 // [256][129]
    float* bs = (float*)smem + 256 * 129;      // 512 floats
    {
        int q = lane >> 2, idq = lane & 3;
#pragma unroll
        for (int mi = 0; mi < 2; mi++)
#pragma unroll
            for (int p = 0; p < 8; p++) {
                int e = wm * 32 + mi * 16 + q;
                int o = wn * 64 + p * 8 + idq * 2;
                buf[o * 129 + e] = acc[mi][p][0];
                buf[(o + 1) * 129 + e] = acc[mi][p][1];
                buf[o * 129 + e + 8] = acc[mi][p][2];
                buf[(o + 1) * 129 + e + 8] = acc[mi][p][3];
            }
    }
    if (MODE == 0) bs[tid] = 0.f;
    __syncthreads();

    const int b = blockIdx.x >> 7;
    const int e0 = (blockIdx.x & 127) * 128;

    // row pass: o-major (g_h0 / out), coalesced float4 stores
    {
        int o = tid >> 1, h = (tid & 1) * 64;
        const float* src = buf + o * 129 + h;
        size_t gbase = ((size_t)b * OUTC + o) * EDGES + e0 + h;
        if (MODE == 0) {
            float s1 = 0.f, s2 = 0.f;
#pragma unroll 4
            for (int i = 0; i < 16; i++) {
                float v0 = src[4 * i], v1 = src[4 * i + 1], v2 = src[4 * i + 2], v3 = src[4 * i + 3];
                *(float4*)(g_h0 + gbase + 4 * i) = make_float4(v0, v1, v2, v3);
                float a;
                a = v0 > 0.f ? v0 : NEG * v0; s1 += a; s2 += a * a;
                a = v1 > 0.f ? v1 : NEG * v1; s1 += a; s2 += a * a;
                a = v2 > 0.f ? v2 : NEG * v2; s1 += a; s2 += a * a;
                a = v3 > 0.f ? v3 : NEG * v3; s1 += a; s2 += a * a;
            }
            atomicAdd(&bs[o], s1);
            atomicAdd(&bs[256 + o], s2);
        } else {
#pragma unroll 4
            for (int i = 0; i < 16; i++) {
                float4 hres = *(const float4*)(g_h0 + gbase + 4 * i);
                float v0 = src[4 * i] + hres.x, v1 = src[4 * i + 1] + hres.y;
                float v2 = src[4 * i + 2] + hres.z, v3 = src[4 * i + 3] + hres.w;
                v0 = v0 > 0.f ? v0 : NEG * v0;
                v1 = v1 > 0.f ? v1 : NEG * v1;
                v2 = v2 > 0.f ? v2 : NEG * v2;
                v3 = v3 > 0.f ? v3 : NEG * v3;
                *(float4*)(outp + gbase + 4 * i) = make_float4(v0, v1, v2, v3);
            }
        }
    }

    if (MODE == 0) {
        // column pass: e-major (g_at = lrelu(h0)), conflict-free strided reads
        {
            int eo = tid >> 6, j = tid & 63;
#pragma unroll 1
            for (int it = 0; it < 16; it++) {
                int e = it * 8 + eo;
                float* dst = g_at + ((size_t)b * EDGES + e0 + e) * C1;
#pragma unroll
                for (int k = 0; k < 4; k++) {
                    int o = j + 64 * k;
                    float v = buf[o * 129 + e];
                    dst[o] = v > 0.f ? v : NEG * v;
                }
            }
        }
        __syncthreads();
        if (tid < 256) {
            atomicAdd(&g_sum1[tid], bs[tid]);
            atomicAdd(&g_sum2[tid], bs[tid + 256]);
        }
    }
}

// ---------------- BN finalize ----------------
__global__ void bn_finalize(const float* __restrict__ gamma, const float* __restrict__ beta) {
    int o = threadIdx.x;
    float n = (float)((size_t)BATCH * EDGES);
    float mean = g_sum1[o] / n;
    float var = g_sum2[o] / n - mean * mean;
    float sc = gamma[o] * rsqrtf(var + BN_EPS_);
    g_scale[o] = sc;
    g_shift[o] = beta[o] - mean * sc;
}

// ---------------- launch ----------------
extern "C" void kernel_launch(void* const* d_in, const int* in_sizes, int n_in,
                              void* d_out, int out_size) {
    (void)in_sizes; (void)n_in; (void)out_size;
    const float* x     = (const float*)d_in[0];
    const int*   gem   = (const int*)d_in[1];
    const float* W0    = (const float*)d_in[2];
    const float* W1    = (const float*)d_in[3];
    const float* gamma = (const float*)d_in[4];
    const float* beta  = (const float*)d_in[5];
    float* out = (float*)d_out;

    cudaFuncSetAttribute(gemm_mma<0>, cudaFuncAttributeMaxDynamicSharedMemorySize, GEMM_SMEM);
    cudaFuncSetAttribute(gemm_mma<1>, cudaFuncAttributeMaxDynamicSharedMemorySize, GEMM_SMEM);

    // order chosen so the 4th launch (ncu sample target) is gemm0
    transpose_x<<<dim3(EDGES / 32, C0 / 32, BATCH), dim3(32, 8)>>>(x);
    prep_wh<0><<<(OUTC * KD0 + 255) / 256, 256>>>(W0);   // also zeroes BN sums
    gather_hf<0><<<BATCH * EDGES * (C0 / 8) / 256, 256>>>(gem);
    gemm_mma<0><<<BATCH * EDGES / 128, 512, GEMM_SMEM>>>(nullptr);  // 4th launch

    bn_finalize<<<1, 256>>>(gamma, beta);
    prep_wh<1><<<(OUTC * KD1 + 255) / 256, 256>>>(W1);

    gather_hf<1><<<BATCH * EDGES * (C1 / 8) / 256, 256>>>(gem);
    gemm_mma<1><<<BATCH * EDGES / 128, 512, GEMM_SMEM>>>(out);
}

// round 12
// speedup vs baseline: 1.1567x; 1.1567x over previous
#include <cuda_runtime.h>
#include <cuda_fp16.h>
#include <cstdint>

#define BATCH 8
#define EDGES 16384
#define C0 128
#define C1 256
#define OUTC 256
#define NEG 0.01f
#define BN_EPS_ 1e-5f

__device__ __half g_W0h[OUTC * 6 * C0];
__device__ __half g_W1h[OUTC * 6 * C1];   // BN-folded
__device__ float g_xt[(size_t)BATCH * EDGES * C0];
__device__ float g_at[(size_t)BATCH * EDGES * C1];   // lrelu(h0), pre-BN, E-major
__device__ float g_h0[(size_t)BATCH * OUTC * EDGES];
__device__ float g_sum1[OUTC], g_sum2[OUTC], g_scale[OUTC], g_shift[OUTC], g_bias[OUTC];

__device__ __forceinline__ uint32_t smem_u32(const void* p) {
    uint32_t a;
    asm("{ .reg .u64 t; cvta.to.shared.u64 t, %1; cvt.u32.u64 %0, t; }" : "=r"(a) : "l"(p));
    return a;
}
__device__ __forceinline__ uint32_t sw64(uint32_t x) { return x ^ ((x >> 3) & 0x30); }
__device__ __forceinline__ void cpa16(uint32_t s, const void* g) {
    asm volatile("cp.async.cg.shared.global [%0], [%1], 16;" :: "r"(s), "l"(g));
}
__device__ __forceinline__ void cpa_commit() { asm volatile("cp.async.commit_group;"); }
__device__ __forceinline__ void ldsm4(uint32_t* r, uint32_t addr) {
    asm volatile("ldmatrix.sync.aligned.m8n8.x4.shared.b16 {%0,%1,%2,%3}, [%4];"
                 : "=r"(r[0]), "=r"(r[1]), "=r"(r[2]), "=r"(r[3]) : "r"(addr));
}
__device__ __forceinline__ void mma16816(float* d, const uint32_t* a, uint32_t b0, uint32_t b1) {
    asm volatile(
        "mma.sync.aligned.m16n8k16.row.col.f32.f16.f16.f32 "
        "{%0,%1,%2,%3}, {%4,%5,%6,%7}, {%8,%9}, {%0,%1,%2,%3};"
        : "+f"(d[0]), "+f"(d[1]), "+f"(d[2]), "+f"(d[3])
        : "r"(a[0]), "r"(a[1]), "r"(a[2]), "r"(a[3]), "r"(b0), "r"(b1));
}
__device__ __forceinline__ void split_pack(float2 v, uint32_t& hi, uint32_t& lo) {
    __half hx = __float2half(v.x), hy = __float2half(v.y);
    __half lx = __float2half(v.x - __half2float(hx));
    __half ly = __float2half(v.y - __half2float(hy));
    hi = (uint32_t)__half_as_ushort(hx) | ((uint32_t)__half_as_ushort(hy) << 16);
    lo = (uint32_t)__half_as_ushort(lx) | ((uint32_t)__half_as_ushort(ly) << 16);
}

__global__ void zero_sums() {
    g_sum1[threadIdx.x] = 0.f;
    g_sum2[threadIdx.x] = 0.f;
}

// K-order: kp = 96b+32p+q; c = 16b+(q&15); jp = 2p+(q>>4); jp: f0,x1,x2,x3,x4,x6
template <int MODE>
__global__ void prep_wh(const float* __restrict__ W) {
    constexpr int C = MODE ? C1 : C0;
    constexpr int K = 6 * C;
    __half* Wh = MODE ? g_W1h : g_W0h;
    int i = blockIdx.x * blockDim.x + threadIdx.x;
    if (i < OUTC * K) {
        int kp = i % K, o = i / K;
        int b = kp / 96, rem = kp % 96;
        int p = rem >> 5, q = rem & 31;
        int c = 16 * b + (q & 15);
        int jp = 2 * p + (q >> 4);
        int jorig = (jp == 5) ? 6 : jp;
        const float* wr = W + (size_t)o * (7 * C) + c * 7;
        float v = wr[jorig];
        if (jp == 1 || jp == 2) v += wr[5];
        if (MODE) {
            float s = g_scale[c];
            v *= (jp <= 2) ? s : ((jp <= 4) ? fabsf(s) : s * s);
        }
        Wh[(size_t)o * K + kp] = __float2half(v);
    }
}

__global__ void bias_k(const float* __restrict__ W1) {
    int o = blockIdx.x, c = threadIdx.x;
    const float* w = W1 + (size_t)o * (7 * C1) + c * 7;
    __shared__ float red[256];
    red[c] = g_shift[c] * (w[0] + 2.f * (w[1] + w[2]) + 4.f * w[5]);
    __syncthreads();
    for (int s = 128; s; s >>= 1) {
        if (c < s) red[c] += red[c + s];
        __syncthreads();
    }
    if (c == 0) g_bias[o] = red[0];
}

__global__ void transpose_x(const float* __restrict__ x) {
    __shared__ float tile[32][33];
    int b = blockIdx.z, e0 = blockIdx.x * 32, c0 = blockIdx.y * 32;
    int tx = threadIdx.x, ty = threadIdx.y;
#pragma unroll
    for (int i = 0; i < 32; i += 8)
        tile[ty + i][tx] = x[((size_t)b * C0 + (c0 + ty + i)) * EDGES + e0 + tx];
    __syncthreads();
#pragma unroll
    for (int i = 0; i < 32; i += 8)
        g_xt[((size_t)b * EDGES + (e0 + ty + i)) * C0 + c0 + tx] = tile[tx][ty + i];
}

// smem: RAW 3x40960 @0 | A 2x16384 @122880 | W 4x16384 @155648 | gemS @221184
#define RAWSZ 40960u
#define AOFF 122880u
#define WOFF 155648u
#define GEMOFF 221184u
#define FUSED_SMEM 223232

template <int MODE>
__global__ __launch_bounds__(512, 1) void gemm_fused(float* __restrict__ outp,
                                                     const int* __restrict__ gem) {
    constexpr int C = MODE ? C1 : C0;
    constexpr int NBLK = C / 16;
    constexpr int T = 3 * NBLK;
    constexpr int K = 6 * C;
    const float* __restrict__ src = MODE ? g_at : g_xt;
    const __half* __restrict__ Wh = MODE ? g_W1h : g_W0h;

    extern __shared__ __align__(1024) char smemc[];
    uint32_t sb = smem_u32(smemc);
    const int tid = threadIdx.x, wid = tid >> 5, lane = tid & 31;
    const int wm = wid & 3, wn = wid >> 2;
    const int eCTA = (blockIdx.x & 127) * 128;
    const int bCTA = blockIdx.x >> 7;
    const float* __restrict__ srcB = src + (size_t)bCTA * EDGES * C;

    int* gemS = (int*)(smemc + GEMOFF);
    gemS[tid] = gem[((size_t)bCTA * EDGES + eCTA) * 4 + tid];
    __syncthreads();

    float acc[2][8][4];
#pragma unroll
    for (int i = 0; i < 2; i++)
#pragma unroll
        for (int j = 0; j < 8; j++)
#pragma unroll
            for (int k = 0; k < 4; k++) acc[i][j][k] = 0.f;

    const int lrW = tid >> 2, lcW = tid & 3;
    auto issueW = [&](int k) {
        uint32_t wd = sb + WOFF + (uint32_t)(k & 3) * 16384u;
        const __half* ws = Wh + k * 32 + (size_t)lrW * K + lcW * 8;
        cpa16(wd + sw64(lrW * 64 + lcW * 16), ws);
        cpa16(wd + sw64((lrW + 128) * 64 + lcW * 16), ws + (size_t)128 * K);
    };
    auto issueRawRow = [&](int blk, int r) {
        int e = tid >> 2, j = tid & 3;
        int rid = (r == 0) ? (eCTA + e) : gemS[e * 4 + (r - 1)];
        const float* sp = srcB + (size_t)rid * C + blk * 16 + j * 4;
        uint32_t d = sb + (uint32_t)(blk % 3) * RAWSZ + (uint32_t)r * 8192u +
                     (uint32_t)e * 64u + (uint32_t)j * 16u;
        cpa16(d, sp);
    };

#pragma unroll
    for (int r = 0; r < 5; r++) issueRawRow(0, r);
    issueW(0); cpa_commit();
#pragma unroll
    for (int r = 0; r < 5; r++) issueRawRow(1, r);
    issueW(1); cpa_commit();
    issueW(2); cpa_commit();

    const int lrow = lane & 15;
    const int lcol = (lane >> 4) * 16;

    for (int t = 0; t <= T; t++) {
        __syncthreads();
        if (t < T) {
            int b = t / 3, p = t - 3 * b;
            if (t >= 1 && t + 2 < T) issueW(t + 2);
            if (b + 2 < NBLK) {
                if (p == 0) { issueRawRow(b + 2, 0); issueRawRow(b + 2, 1); }
                else if (p == 1) { issueRawRow(b + 2, 2); issueRawRow(b + 2, 3); }
                else issueRawRow(b + 2, 4);
            }
            cpa_commit();
            asm volatile("cp.async.wait_group 3;");
        } else {
            asm volatile("cp.async.wait_group 0;");
        }
        __syncthreads();

        if (t < T) {  // convert stage t -> A slot t&1
            int b = t / 3, p = t - 3 * b;
            const char* rawB = smemc + (size_t)(b % 3) * RAWSZ;
            char* AH = smemc + AOFF + (size_t)(t & 1) * 16384;
            char* AL = AH + 8192;
#pragma unroll
            for (int kk = 0; kk < 2; kk++) {
                int u = tid + kk * 512;
                int e = u >> 3, cp = u & 7;
                const char* rb = rawB + e * 64 + cp * 8;
                float2 F0, F1;
                if (p == 0) {
                    float2 f0 = *(const float2*)(rb);
                    float2 f1 = *(const float2*)(rb + 8192);
                    float2 f3 = *(const float2*)(rb + 24576);
                    F0 = f0;
                    F1 = make_float2(f1.x + f3.x, f1.y + f3.y);
                } else if (p == 1) {
                    float2 f1 = *(const float2*)(rb + 8192);
                    float2 f2 = *(const float2*)(rb + 16384);
                    float2 f3 = *(const float2*)(rb + 24576);
                    float2 f4 = *(const float2*)(rb + 32768);
                    F0 = make_float2(f2.x + f4.x, f2.y + f4.y);
                    F1 = make_float2(fabsf(f1.x - f3.x), fabsf(f1.y - f3.y));
                } else {
                    float2 f1 = *(const float2*)(rb + 8192);
                    float2 f2 = *(const float2*)(rb + 16384);
                    float2 f3 = *(const float2*)(rb + 24576);
                    float2 f4 = *(const float2*)(rb + 32768);
                    F0 = make_float2(fabsf(f2.x - f4.x), fabsf(f2.y - f4.y));
                    float x1 = f1.x + f3.x, x2 = f2.x + f4.x, avg = 0.25f * (x1 + x2);
                    float d1 = f1.x - avg, d2 = f2.x - avg, d3 = f3.x - avg, d4 = f4.x - avg;
                    F1.x = d1 * d1 + d2 * d2 + d3 * d3 + d4 * d4;
                    x1 = f1.y + f3.y; x2 = f2.y + f4.y; avg = 0.25f * (x1 + x2);
                    d1 = f1.y - avg; d2 = f2.y - avg; d3 = f3.y - avg; d4 = f4.y - avg;
                    F1.y = d1 * d1 + d2 * d2 + d3 * d3 + d4 * d4;
                }
                uint32_t h0p, l0p, h1p, l1p;
                split_pack(F0, h0p, l0p);
                split_pack(F1, h1p, l1p);
                uint32_t off0 = sw64((uint32_t)(e * 64 + cp * 4));
                uint32_t off1 = sw64((uint32_t)(e * 64 + 32 + cp * 4));
                *(uint32_t*)(AH + off0) = h0p;
                *(uint32_t*)(AL + off0) = l0p;
                *(uint32_t*)(AH + off1) = h1p;
                *(uint32_t*)(AL + off1) = l1p;
            }
        }
        if (t >= 1) {  // MMA stage t-1
            int st = t - 1;
            uint32_t AHs = sb + AOFF + (uint32_t)(st & 1) * 16384u;
            uint32_t ALs = AHs + 8192u;
            uint32_t Ws = sb + WOFF + (uint32_t)(st & 3) * 16384u;
#pragma unroll
            for (int ks = 0; ks < 2; ks++) {
                int ko = ks * 32;
                uint32_t ah[2][4], al[2][4], bb[4][4];
#pragma unroll
                for (int mi = 0; mi < 2; mi++) {
                    uint32_t ao = sw64((wm * 32 + mi * 16 + lrow) * 64 + ko + lcol);
                    ldsm4(ah[mi], AHs + ao);
                    ldsm4(al[mi], ALs + ao);
                }
#pragma unroll
                for (int nj = 0; nj < 4; nj++)
                    ldsm4(bb[nj], Ws + sw64((wn * 64 + nj * 16 + lrow) * 64 + ko + lcol));
#pragma unroll
                for (int mi = 0; mi < 2; mi++)
#pragma unroll
                    for (int nj = 0; nj < 4; nj++) {
                        mma16816(acc[mi][2 * nj], ah[mi], bb[nj][0], bb[nj][2]);
                        mma16816(acc[mi][2 * nj + 1], ah[mi], bb[nj][1], bb[nj][3]);
                    }
#pragma unroll
                for (int mi = 0; mi < 2; mi++)
#pragma unroll
                    for (int nj = 0; nj < 4; nj++) {
                        mma16816(acc[mi][2 * nj], al[mi], bb[nj][0], bb[nj][2]);
                        mma16816(acc[mi][2 * nj + 1], al[mi], bb[nj][1], bb[nj][3]);
                    }
            }
        }
    }

    // ---------------- epilogue ----------------
    __syncthreads();
    float* buf = (float*)smemc;                    // [256][129]
    float* bs = (float*)(smemc + 256 * 129 * 4);   // 512 floats
    {
        int q = lane >> 2, idq = lane & 3;
#pragma unroll
        for (int mi = 0; mi < 2; mi++)
#pragma unroll
            for (int p = 0; p < 8; p++) {
                int e = wm * 32 + mi * 16 + q;
                int o = wn * 64 + p * 8 + idq * 2;
                buf[o * 129 + e] = acc[mi][p][0];
                buf[(o + 1) * 129 + e] = acc[mi][p][1];
                buf[o * 129 + e + 8] = acc[mi][p][2];
                buf[(o + 1) * 129 + e + 8] = acc[mi][p][3];
            }
    }
    if (MODE == 0) bs[tid] = 0.f;
    __syncthreads();

    {
        int o = tid >> 1, h = (tid & 1) * 64;
        const float* srow = buf + o * 129 + h;
        size_t gbase = ((size_t)bCTA * OUTC + o) * EDGES + eCTA + h;
        if (MODE == 0) {
            float s1 = 0.f, s2 = 0.f;
#pragma unroll 4
            for (int i = 0; i < 16; i++) {
                float v0 = srow[4 * i], v1 = srow[4 * i + 1], v2 = srow[4 * i + 2], v3 = srow[4 * i + 3];
                *(float4*)(g_h0 + gbase + 4 * i) = make_float4(v0, v1, v2, v3);
                float a;
                a = v0 > 0.f ? v0 : NEG * v0; s1 += a; s2 += a * a;
                a = v1 > 0.f ? v1 : NEG * v1; s1 += a; s2 += a * a;
                a = v2 > 0.f ? v2 : NEG * v2; s1 += a; s2 += a * a;
                a = v3 > 0.f ? v3 : NEG * v3; s1 += a; s2 += a * a;
            }
            atomicAdd(&bs[o], s1);
            atomicAdd(&bs[256 + o], s2);
        } else {
            float bo = g_bias[o];
#pragma unroll 4
            for (int i = 0; i < 16; i++) {
                float4 hres = *(const float4*)(g_h0 + gbase + 4 * i);
                float v0 = srow[4 * i] + bo + hres.x, v1 = srow[4 * i + 1] + bo + hres.y;
                float v2 = srow[4 * i + 2] + bo + hres.z, v3 = srow[4 * i + 3] + bo + hres.w;
                v0 = v0 > 0.f ? v0 : NEG * v0;
                v1 = v1 > 0.f ? v1 : NEG * v1;
                v2 = v2 > 0.f ? v2 : NEG * v2;
                v3 = v3 > 0.f ? v3 : NEG * v3;
                *(float4*)(outp + gbase + 4 * i) = make_float4(v0, v1, v2, v3);
            }
        }
    }

    if (MODE == 0) {
        int eo = tid >> 6, j = tid & 63;
#pragma unroll 1
        for (int it = 0; it < 16; it++) {
            int e = it * 8 + eo;
            float* dst = g_at + ((size_t)bCTA * EDGES + eCTA + e) * C1;
#pragma unroll
            for (int k = 0; k < 4; k++) {
                int o = j + 64 * k;
                float v = buf[o * 129 + e];
                dst[o] = v > 0.f ? v : NEG * v;
            }
        }
        __syncthreads();
        if (tid < 256) {
            atomicAdd(&g_sum1[tid], bs[tid]);
            atomicAdd(&g_sum2[tid], bs[tid + 256]);
        }
    }
}

__global__ void bn_finalize(const float* __restrict__ gamma, const float* __restrict__ beta) {
    int o = threadIdx.x;
    float n = (float)((size_t)BATCH * EDGES);
    float mean = g_sum1[o] / n;
    float var = g_sum2[o] / n - mean * mean;
    float sc = gamma[o] * rsqrtf(var + BN_EPS_);
    g_scale[o] = sc;
    g_shift[o] = beta[o] - mean * sc;
}

extern "C" void kernel_launch(void* const* d_in, const int* in_sizes, int n_in,
                              void* d_out, int out_size) {
    (void)in_sizes; (void)n_in; (void)out_size;
    const float* x     = (const float*)d_in[0];
    const int*   gem   = (const int*)d_in[1];
    const float* W0    = (const float*)d_in[2];
    const float* W1    = (const float*)d_in[3];
    const float* gamma = (const float*)d_in[4];
    const float* beta  = (const float*)d_in[5];
    float* out = (float*)d_out;

    cudaFuncSetAttribute(gemm_fused<0>, cudaFuncAttributeMaxDynamicSharedMemorySize, FUSED_SMEM);
    cudaFuncSetAttribute(gemm_fused<1>, cudaFuncAttributeMaxDynamicSharedMemorySize, FUSED_SMEM);

    // 4th launch = gemm_fused<0> (ncu sample target)
    zero_sums<<<1, 256>>>();
    transpose_x<<<dim3(EDGES / 32, C0 / 32, BATCH), dim3(32, 8)>>>(x);
    prep_wh<0><<<(OUTC * 6 * C0 + 255) / 256, 256>>>(W0);
    gemm_fused<0><<<BATCH * EDGES / 128, 512, FUSED_SMEM>>>(nullptr, gem);

    bn_finalize<<<1, 256>>>(gamma, beta);
    prep_wh<1><<<(OUTC * 6 * C1 + 255) / 256, 256>>>(W1);
    bias_k<<<256, 256>>>(W1);

    gemm_fused<1><<<BATCH * EDGES / 128, 512, FUSED_SMEM>>>(out, gem);
}

// round 13
// speedup vs baseline: 1.2377x; 1.0700x over previous
#include <cuda_runtime.h>
#include <cuda_fp16.h>
#include <cstdint>

#define BATCH 8
#define EDGES 16384
#define C0 128
#define C1 256
#define OUTC 256
#define NEG 0.01f
#define BN_EPS_ 1e-5f

__device__ __half g_W0h[OUTC * 6 * C0];
__device__ __half g_W1h[OUTC * 6 * C1];   // BN-folded
__device__ float g_xt[(size_t)BATCH * EDGES * C0];
__device__ float g_at[(size_t)BATCH * EDGES * C1];   // lrelu(h0), pre-BN, E-major
__device__ float g_sum1[OUTC], g_sum2[OUTC], g_scale[OUTC], g_shift[OUTC], g_bias[OUTC];

__device__ __forceinline__ uint32_t smem_u32(const void* p) {
    uint32_t a;
    asm("{ .reg .u64 t; cvta.to.shared.u64 t, %1; cvt.u32.u64 %0, t; }" : "=r"(a) : "l"(p));
    return a;
}
__device__ __forceinline__ uint32_t sw64(uint32_t x) { return x ^ ((x >> 3) & 0x30); }
__device__ __forceinline__ void cpa16(uint32_t s, const void* g) {
    asm volatile("cp.async.cg.shared.global [%0], [%1], 16;" :: "r"(s), "l"(g));
}
__device__ __forceinline__ void cpa_commit() { asm volatile("cp.async.commit_group;"); }
__device__ __forceinline__ void ldsm4(uint32_t* r, uint32_t addr) {
    asm volatile("ldmatrix.sync.aligned.m8n8.x4.shared.b16 {%0,%1,%2,%3}, [%4];"
                 : "=r"(r[0]), "=r"(r[1]), "=r"(r[2]), "=r"(r[3]) : "r"(addr));
}
__device__ __forceinline__ void mma16816(float* d, const uint32_t* a, uint32_t b0, uint32_t b1) {
    asm volatile(
        "mma.sync.aligned.m16n8k16.row.col.f32.f16.f16.f32 "
        "{%0,%1,%2,%3}, {%4,%5,%6,%7}, {%8,%9}, {%0,%1,%2,%3};"
        : "+f"(d[0]), "+f"(d[1]), "+f"(d[2]), "+f"(d[3])
        : "r"(a[0]), "r"(a[1]), "r"(a[2]), "r"(a[3]), "r"(b0), "r"(b1));
}
__device__ __forceinline__ void split_pack(float2 v, uint32_t& hi, uint32_t& lo) {
    __half2 h = __float22half2_rn(v);
    float2 hf = __half22float2(h);
    __half2 l = __float22half2_rn(make_float2(v.x - hf.x, v.y - hf.y));
    hi = *reinterpret_cast<uint32_t*>(&h);
    lo = *reinterpret_cast<uint32_t*>(&l);
}

__global__ void zero_sums() {
    g_sum1[threadIdx.x] = 0.f;
    g_sum2[threadIdx.x] = 0.f;
}

// K-order: kp = 96b+32p+q; c = 16b+(q&15); jp = 2p+(q>>4); jp: f0,x1,x2,x3,x4,x6
template <int MODE>
__global__ void prep_wh(const float* __restrict__ W) {
    constexpr int C = MODE ? C1 : C0;
    constexpr int K = 6 * C;
    __half* Wh = MODE ? g_W1h : g_W0h;
    int i = blockIdx.x * blockDim.x + threadIdx.x;
    if (i < OUTC * K) {
        int kp = i % K, o = i / K;
        int b = kp / 96, rem = kp % 96;
        int p = rem >> 5, q = rem & 31;
        int c = 16 * b + (q & 15);
        int jp = 2 * p + (q >> 4);
        int jorig = (jp == 5) ? 6 : jp;
        const float* wr = W + (size_t)o * (7 * C) + c * 7;
        float v = wr[jorig];
        if (jp == 1 || jp == 2) v += wr[5];
        if (MODE) {
            float s = g_scale[c];
            v *= (jp <= 2) ? s : ((jp <= 4) ? fabsf(s) : s * s);
        }
        Wh[(size_t)o * K + kp] = __float2half(v);
    }
}

__global__ void bias_k(const float* __restrict__ W1) {
    int o = blockIdx.x, c = threadIdx.x;
    const float* w = W1 + (size_t)o * (7 * C1) + c * 7;
    __shared__ float red[256];
    red[c] = g_shift[c] * (w[0] + 2.f * (w[1] + w[2]) + 4.f * w[5]);
    __syncthreads();
    for (int s = 128; s; s >>= 1) {
        if (c < s) red[c] += red[c + s];
        __syncthreads();
    }
    if (c == 0) g_bias[o] = red[0];
}

__global__ void transpose_x(const float* __restrict__ x) {
    __shared__ float tile[32][33];
    int b = blockIdx.z, e0 = blockIdx.x * 32, c0 = blockIdx.y * 32;
    int tx = threadIdx.x, ty = threadIdx.y;
#pragma unroll
    for (int i = 0; i < 32; i += 8)
        tile[ty + i][tx] = x[((size_t)b * C0 + (c0 + ty + i)) * EDGES + e0 + tx];
    __syncthreads();
#pragma unroll
    for (int i = 0; i < 32; i += 8)
        g_xt[((size_t)b * EDGES + (e0 + ty + i)) * C0 + c0 + tx] = tile[tx][ty + i];
}

// smem: RAW 3x40960 @0 | A 2x16384 @122880 | W 4x16384 @155648 | gemS @221184
#define RAWSZ 40960u
#define AOFF 122880u
#define WOFF 155648u
#define GEMOFF 221184u
#define FUSED_SMEM 223232

template <int MODE>
__global__ __launch_bounds__(512, 1) void gemm_fused(float* __restrict__ outp,
                                                     const int* __restrict__ gem) {
    constexpr int C = MODE ? C1 : C0;
    constexpr int NBLK = C / 16;
    constexpr int T = 3 * NBLK;
    constexpr int K = 6 * C;
    const float* __restrict__ src = MODE ? g_at : g_xt;
    const __half* __restrict__ Wh = MODE ? g_W1h : g_W0h;

    extern __shared__ __align__(1024) char smemc[];
    uint32_t sb = smem_u32(smemc);
    const int tid = threadIdx.x, wid = tid >> 5, lane = tid & 31;
    const int wm = wid & 3, wn = wid >> 2;
    const int eCTA = (blockIdx.x & 127) * 128;
    const int bCTA = blockIdx.x >> 7;
    const float* __restrict__ srcB = src + (size_t)bCTA * EDGES * C;

    int* gemS = (int*)(smemc + GEMOFF);
    gemS[tid] = gem[((size_t)bCTA * EDGES + eCTA) * 4 + tid];
    __syncthreads();

    float acc[2][8][4];
#pragma unroll
    for (int i = 0; i < 2; i++)
#pragma unroll
        for (int j = 0; j < 8; j++)
#pragma unroll
            for (int k = 0; k < 4; k++) acc[i][j][k] = 0.f;

    const int lrW = tid >> 2, lcW = tid & 3;
    auto issueW = [&](int k) {
        uint32_t wd = sb + WOFF + (uint32_t)(k & 3) * 16384u;
        const __half* ws = Wh + k * 32 + (size_t)lrW * K + lcW * 8;
        cpa16(wd + sw64(lrW * 64 + lcW * 16), ws);
        cpa16(wd + sw64((lrW + 128) * 64 + lcW * 16), ws + (size_t)128 * K);
    };
    auto issueRawRow = [&](int blk, int r) {
        int e = tid >> 2, j = tid & 3;
        int rid = (r == 0) ? (eCTA + e) : gemS[e * 4 + (r - 1)];
        const float* sp = srcB + (size_t)rid * C + blk * 16 + j * 4;
        uint32_t d = sb + (uint32_t)(blk % 3) * RAWSZ + (uint32_t)r * 8192u +
                     (uint32_t)e * 64u + (uint32_t)j * 16u;
        cpa16(d, sp);
    };

#pragma unroll
    for (int r = 0; r < 5; r++) issueRawRow(0, r);
    issueW(0); cpa_commit();
#pragma unroll
    for (int r = 0; r < 5; r++) issueRawRow(1, r);
    issueW(1); cpa_commit();
    issueW(2); cpa_commit();

    const int lrow = lane & 15;
    const int lcol = (lane >> 4) * 16;

    for (int t = 0; t <= T; t++) {
        __syncthreads();
        if (t < T) {
            int b = t / 3, p = t - 3 * b;
            if (t >= 1 && t + 2 < T) issueW(t + 2);
            if (b + 2 < NBLK) {
                if (p == 0) { issueRawRow(b + 2, 0); issueRawRow(b + 2, 1); }
                else if (p == 1) { issueRawRow(b + 2, 2); issueRawRow(b + 2, 3); }
                else issueRawRow(b + 2, 4);
            }
            cpa_commit();
            asm volatile("cp.async.wait_group 3;");
        } else {
            asm volatile("cp.async.wait_group 0;");
        }
        __syncthreads();

        if (t < T) {  // convert stage t -> A slot t&1
            int b = t / 3, p = t - 3 * b;
            const char* rawB = smemc + (size_t)(b % 3) * RAWSZ;
            char* AH = smemc + AOFF + (size_t)(t & 1) * 16384;
            char* AL = AH + 8192;
#pragma unroll
            for (int kk = 0; kk < 2; kk++) {
                int u = tid + kk * 512;
                int e = u >> 3, cp = u & 7;
                const char* rb = rawB + e * 64 + cp * 8;
                float2 F0, F1;
                if (p == 0) {
                    float2 f0 = *(const float2*)(rb);
                    float2 f1 = *(const float2*)(rb + 8192);
                    float2 f3 = *(const float2*)(rb + 24576);
                    F0 = f0;
                    F1 = make_float2(f1.x + f3.x, f1.y + f3.y);
                } else if (p == 1) {
                    float2 f1 = *(const float2*)(rb + 8192);
                    float2 f2 = *(const float2*)(rb + 16384);
                    float2 f3 = *(const float2*)(rb + 24576);
                    float2 f4 = *(const float2*)(rb + 32768);
                    F0 = make_float2(f2.x + f4.x, f2.y + f4.y);
                    F1 = make_float2(fabsf(f1.x - f3.x), fabsf(f1.y - f3.y));
                } else {
                    float2 f1 = *(const float2*)(rb + 8192);
                    float2 f2 = *(const float2*)(rb + 16384);
                    float2 f3 = *(const float2*)(rb + 24576);
                    float2 f4 = *(const float2*)(rb + 32768);
                    F0 = make_float2(fabsf(f2.x - f4.x), fabsf(f2.y - f4.y));
                    float x1 = f1.x + f3.x, x2 = f2.x + f4.x, avg = 0.25f * (x1 + x2);
                    float d1 = f1.x - avg, d2 = f2.x - avg, d3 = f3.x - avg, d4 = f4.x - avg;
                    F1.x = d1 * d1 + d2 * d2 + d3 * d3 + d4 * d4;
                    x1 = f1.y + f3.y; x2 = f2.y + f4.y; avg = 0.25f * (x1 + x2);
                    d1 = f1.y - avg; d2 = f2.y - avg; d3 = f3.y - avg; d4 = f4.y - avg;
                    F1.y = d1 * d1 + d2 * d2 + d3 * d3 + d4 * d4;
                }
                uint32_t h0p, l0p, h1p, l1p;
                split_pack(F0, h0p, l0p);
                split_pack(F1, h1p, l1p);
                uint32_t off0 = sw64((uint32_t)(e * 64 + cp * 4));
                uint32_t off1 = sw64((uint32_t)(e * 64 + 32 + cp * 4));
                *(uint32_t*)(AH + off0) = h0p;
                *(uint32_t*)(AL + off0) = l0p;
                *(uint32_t*)(AH + off1) = h1p;
                *(uint32_t*)(AL + off1) = l1p;
            }
        }
        if (t >= 1) {  // MMA stage t-1
            int st = t - 1;
            uint32_t AHs = sb + AOFF + (uint32_t)(st & 1) * 16384u;
            uint32_t ALs = AHs + 8192u;
            uint32_t Ws = sb + WOFF + (uint32_t)(st & 3) * 16384u;
#pragma unroll
            for (int ks = 0; ks < 2; ks++) {
                int ko = ks * 32;
                uint32_t ah[2][4], al[2][4], bb[4][4];
#pragma unroll
                for (int mi = 0; mi < 2; mi++) {
                    uint32_t ao = sw64((wm * 32 + mi * 16 + lrow) * 64 + ko + lcol);
                    ldsm4(ah[mi], AHs + ao);
                    ldsm4(al[mi], ALs + ao);
                }
#pragma unroll
                for (int nj = 0; nj < 4; nj++)
                    ldsm4(bb[nj], Ws + sw64((wn * 64 + nj * 16 + lrow) * 64 + ko + lcol));
#pragma unroll
                for (int mi = 0; mi < 2; mi++)
#pragma unroll
                    for (int nj = 0; nj < 4; nj++) {
                        mma16816(acc[mi][2 * nj], ah[mi], bb[nj][0], bb[nj][2]);
                        mma16816(acc[mi][2 * nj + 1], ah[mi], bb[nj][1], bb[nj][3]);
                    }
#pragma unroll
                for (int mi = 0; mi < 2; mi++)
#pragma unroll
                    for (int nj = 0; nj < 4; nj++) {
                        mma16816(acc[mi][2 * nj], al[mi], bb[nj][0], bb[nj][2]);
                        mma16816(acc[mi][2 * nj + 1], al[mi], bb[nj][1], bb[nj][3]);
                    }
            }
        }
    }

    // ---------------- epilogue ----------------
    __syncthreads();
    float* buf = (float*)smemc;                    // [256][129]
    float* bs = (float*)(smemc + 256 * 129 * 4);   // 512 floats
    {
        int q = lane >> 2, idq = lane & 3;
#pragma unroll
        for (int mi = 0; mi < 2; mi++)
#pragma unroll
            for (int p = 0; p < 8; p++) {
                int e = wm * 32 + mi * 16 + q;
                int o = wn * 64 + p * 8 + idq * 2;
                buf[o * 129 + e] = acc[mi][p][0];
                buf[(o + 1) * 129 + e] = acc[mi][p][1];
                buf[o * 129 + e + 8] = acc[mi][p][2];
                buf[(o + 1) * 129 + e + 8] = acc[mi][p][3];
            }
    }
    if (MODE == 0) bs[tid] = 0.f;
    __syncthreads();

    if (MODE == 0) {
        // e-major pass only: g_at = lrelu(h0), with fused BN stats
        int eo = tid >> 6, j = tid & 63;
        float s1[4] = {0.f, 0.f, 0.f, 0.f}, s2[4] = {0.f, 0.f, 0.f, 0.f};
#pragma unroll 1
        for (int it = 0; it < 16; it++) {
            int e = it * 8 + eo;
            float* dst = g_at + ((size_t)bCTA * EDGES + eCTA + e) * C1;
#pragma unroll
            for (int k = 0; k < 4; k++) {
                int o = j + 64 * k;
                float v = buf[o * 129 + e];
                float a = v > 0.f ? v : NEG * v;
                dst[o] = a;
                s1[k] += a;
                s2[k] += a * a;
            }
        }
#pragma unroll
        for (int k = 0; k < 4; k++) {
            atomicAdd(&bs[j + 64 * k], s1[k]);
            atomicAdd(&bs[256 + j + 64 * k], s2[k]);
        }
        __syncthreads();
        if (tid < 256) {
            atomicAdd(&g_sum1[tid], bs[tid]);
            atomicAdd(&g_sum2[tid], bs[tid + 256]);
        }
    } else {
        // residual add: h0 = inv_lrelu(g_at), accumulate into buf
        {
            int e = tid >> 2, j = tid & 3;
            const float* at_row = g_at + ((size_t)bCTA * EDGES + eCTA + e) * C1 + j * 64;
#pragma unroll 4
            for (int i = 0; i < 16; i++) {
                float4 av = *(const float4*)(at_row + 4 * i);
                float h0 = av.x > 0.f ? av.x : av.x * 100.f;
                float h1 = av.y > 0.f ? av.y : av.y * 100.f;
                float h2 = av.z > 0.f ? av.z : av.z * 100.f;
                float h3 = av.w > 0.f ? av.w : av.w * 100.f;
                int o = j * 64 + 4 * i;
                buf[(o + 0) * 129 + e] += h0;
                buf[(o + 1) * 129 + e] += h1;
                buf[(o + 2) * 129 + e] += h2;
                buf[(o + 3) * 129 + e] += h3;
            }
        }
        __syncthreads();
        // row pass: o-major coalesced output
        int o = tid >> 1, hh = (tid & 1) * 64;
        float bo = g_bias[o];
        const float* srow = buf + o * 129 + hh;
        size_t gbase = ((size_t)bCTA * OUTC + o) * EDGES + eCTA + hh;
#pragma unroll 4
        for (int i = 0; i < 16; i++) {
            float v0 = srow[4 * i] + bo, v1 = srow[4 * i + 1] + bo;
            float v2 = srow[4 * i + 2] + bo, v3 = srow[4 * i + 3] + bo;
            v0 = v0 > 0.f ? v0 : NEG * v0;
            v1 = v1 > 0.f ? v1 : NEG * v1;
            v2 = v2 > 0.f ? v2 : NEG * v2;
            v3 = v3 > 0.f ? v3 : NEG * v3;
            *(float4*)(outp + gbase + 4 * i) = make_float4(v0, v1, v2, v3);
        }
    }
}

__global__ void bn_finalize(const float* __restrict__ gamma, const float* __restrict__ beta) {
    int o = threadIdx.x;
    float n = (float)((size_t)BATCH * EDGES);
    float mean = g_sum1[o] / n;
    float var = g_sum2[o] / n - mean * mean;
    float sc = gamma[o] * rsqrtf(var + BN_EPS_);
    g_scale[o] = sc;
    g_shift[o] = beta[o] - mean * sc;
}

extern "C" void kernel_launch(void* const* d_in, const int* in_sizes, int n_in,
                              void* d_out, int out_size) {
    (void)in_sizes; (void)n_in; (void)out_size;
    const float* x     = (const float*)d_in[0];
    const int*   gem   = (const int*)d_in[1];
    const float* W0    = (const float*)d_in[2];
    const float* W1    = (const float*)d_in[3];
    const float* gamma = (const float*)d_in[4];
    const float* beta  = (const float*)d_in[5];
    float* out = (float*)d_out;

    cudaFuncSetAttribute(gemm_fused<0>, cudaFuncAttributeMaxDynamicSharedMemorySize, FUSED_SMEM);
    cudaFuncSetAttribute(gemm_fused<1>, cudaFuncAttributeMaxDynamicSharedMemorySize, FUSED_SMEM);

    // 4th launch = gemm_fused<0> (ncu sample target)
    zero_sums<<<1, 256>>>();
    transpose_x<<<dim3(EDGES / 32, C0 / 32, BATCH), dim3(32, 8)>>>(x);
    prep_wh<0><<<(OUTC * 6 * C0 + 255) / 256, 256>>>(W0);
    gemm_fused<0><<<BATCH * EDGES / 128, 512, FUSED_SMEM>>>(nullptr, gem);

    bn_finalize<<<1, 256>>>(gamma, beta);
    prep_wh<1><<<(OUTC * 6 * C1 + 255) / 256, 256>>>(W1);
    bias_k<<<256, 256>>>(W1);

    gemm_fused<1><<<BATCH * EDGES / 128, 512, FUSED_SMEM>>>(out, gem);
}

// round 14
// speedup vs baseline: 1.7475x; 1.4119x over previous
#include <cuda_runtime.h>
#include <cuda_fp16.h>
#include <cstdint>

#define BATCH 8
#define EDGES 16384
#define C0 128
#define C1 256
#define OUTC 256
#define NEG 0.01f
#define BN_EPS_ 1e-5f

__device__ __half g_W0h[OUTC * 6 * C0];
__device__ __half g_W1h[OUTC * 6 * C1];   // BN-folded
__device__ float g_xt[(size_t)BATCH * EDGES * C0];
__device__ float g_at[(size_t)BATCH * EDGES * C1];   // lrelu(h0), pre-BN, E-major
__device__ float g_sum1[OUTC], g_sum2[OUTC], g_scale[OUTC], g_shift[OUTC], g_bias[OUTC];

__device__ __forceinline__ uint32_t smem_u32(const void* p) {
    uint32_t a;
    asm("{ .reg .u64 t; cvta.to.shared.u64 t, %1; cvt.u32.u64 %0, t; }" : "=r"(a) : "l"(p));
    return a;
}
__device__ __forceinline__ uint32_t sw64(uint32_t x) { return x ^ ((x >> 3) & 0x30); }
__device__ __forceinline__ void cpa16(uint32_t s, const void* g) {
    asm volatile("cp.async.cg.shared.global [%0], [%1], 16;" :: "r"(s), "l"(g));
}
__device__ __forceinline__ void cpa_commit() { asm volatile("cp.async.commit_group;"); }
__device__ __forceinline__ void ldsm4(uint32_t* r, uint32_t addr) {
    asm volatile("ldmatrix.sync.aligned.m8n8.x4.shared.b16 {%0,%1,%2,%3}, [%4];"
                 : "=r"(r[0]), "=r"(r[1]), "=r"(r[2]), "=r"(r[3]) : "r"(addr));
}
__device__ __forceinline__ void mma16816(float* d, const uint32_t* a, uint32_t b0, uint32_t b1) {
    asm volatile(
        "mma.sync.aligned.m16n8k16.row.col.f32.f16.f16.f32 "
        "{%0,%1,%2,%3}, {%4,%5,%6,%7}, {%8,%9}, {%0,%1,%2,%3};"
        : "+f"(d[0]), "+f"(d[1]), "+f"(d[2]), "+f"(d[3])
        : "r"(a[0]), "r"(a[1]), "r"(a[2]), "r"(a[3]), "r"(b0), "r"(b1));
}

__global__ void zero_sums() {
    g_sum1[threadIdx.x] = 0.f;
    g_sum2[threadIdx.x] = 0.f;
}

// K-order: kp = 96b+32p+q; c = 16b+(q&15); jp = 2p+(q>>4); jp: f0,x1,x2,x3,x4,x6
template <int MODE>
__global__ void prep_wh(const float* __restrict__ W) {
    constexpr int C = MODE ? C1 : C0;
    constexpr int K = 6 * C;
    __half* Wh = MODE ? g_W1h : g_W0h;
    int i = blockIdx.x * blockDim.x + threadIdx.x;
    if (i < OUTC * K) {
        int kp = i % K, o = i / K;
        int b = kp / 96, rem = kp % 96;
        int p = rem >> 5, q = rem & 31;
        int c = 16 * b + (q & 15);
        int jp = 2 * p + (q >> 4);
        int jorig = (jp == 5) ? 6 : jp;
        const float* wr = W + (size_t)o * (7 * C) + c * 7;
        float v = wr[jorig];
        if (jp == 1 || jp == 2) v += wr[5];
        if (MODE) {
            float s = g_scale[c];
            v *= (jp <= 2) ? s : ((jp <= 4) ? fabsf(s) : s * s);
        }
        Wh[(size_t)o * K + kp] = __float2half(v);
    }
}

__global__ void bias_k(const float* __restrict__ W1) {
    int o = blockIdx.x, c = threadIdx.x;
    const float* w = W1 + (size_t)o * (7 * C1) + c * 7;
    __shared__ float red[256];
    red[c] = g_shift[c] * (w[0] + 2.f * (w[1] + w[2]) + 4.f * w[5]);
    __syncthreads();
    for (int s = 128; s; s >>= 1) {
        if (c < s) red[c] += red[c + s];
        __syncthreads();
    }
    if (c == 0) g_bias[o] = red[0];
}

__global__ void transpose_x(const float* __restrict__ x) {
    __shared__ float tile[32][33];
    int b = blockIdx.z, e0 = blockIdx.x * 32, c0 = blockIdx.y * 32;
    int tx = threadIdx.x, ty = threadIdx.y;
#pragma unroll
    for (int i = 0; i < 32; i += 8)
        tile[ty + i][tx] = x[((size_t)b * C0 + (c0 + ty + i)) * EDGES + e0 + tx];
    __syncthreads();
#pragma unroll
    for (int i = 0; i < 32; i += 8)
        g_xt[((size_t)b * EDGES + (e0 + ty + i)) * C0 + c0 + tx] = tile[tx][ty + i];
}

// smem: RAW 3x40960 @0 | A 2x8192 @122880 | W 4x16384 @139264 | gemS @204800
#define RAWSZ 40960u
#define AOFF 122880u
#define WOFF 139264u
#define GEMOFF 204800u
#define FUSED_SMEM 206848

template <int MODE>
__global__ __launch_bounds__(512, 1) void gemm_fused(float* __restrict__ outp,
                                                     const int* __restrict__ gem) {
    constexpr int C = MODE ? C1 : C0;
    constexpr int NBLK = C / 16;
    constexpr int T = 3 * NBLK;
    constexpr int K = 6 * C;
    const float* __restrict__ src = MODE ? g_at : g_xt;
    const __half* __restrict__ Wh = MODE ? g_W1h : g_W0h;

    extern __shared__ __align__(1024) char smemc[];
    uint32_t sb = smem_u32(smemc);
    const int tid = threadIdx.x, wid = tid >> 5, lane = tid & 31;
    const int wm = wid & 3, wn = wid >> 2;
    const int eCTA = (blockIdx.x & 127) * 128;
    const int bCTA = blockIdx.x >> 7;
    const float* __restrict__ srcB = src + (size_t)bCTA * EDGES * C;

    int* gemS = (int*)(smemc + GEMOFF);
    gemS[tid] = gem[((size_t)bCTA * EDGES + eCTA) * 4 + tid];
    __syncthreads();

    float acc[2][8][4];
#pragma unroll
    for (int i = 0; i < 2; i++)
#pragma unroll
        for (int j = 0; j < 8; j++)
#pragma unroll
            for (int k = 0; k < 4; k++) acc[i][j][k] = 0.f;

    const int lrW = tid >> 2, lcW = tid & 3;
    auto issueW = [&](int k) {
        uint32_t wd = sb + WOFF + (uint32_t)(k & 3) * 16384u;
        const __half* ws = Wh + k * 32 + (size_t)lrW * K + lcW * 8;
        cpa16(wd + sw64(lrW * 64 + lcW * 16), ws);
        cpa16(wd + sw64((lrW + 128) * 64 + lcW * 16), ws + (size_t)128 * K);
    };
    auto issueRawRow = [&](int blk, int r) {
        int e = tid >> 2, j = tid & 3;
        int rid = (r == 0) ? (eCTA + e) : gemS[e * 4 + (r - 1)];
        const float* sp = srcB + (size_t)rid * C + blk * 16 + j * 4;
        uint32_t d = sb + (uint32_t)(blk % 3) * RAWSZ + (uint32_t)r * 8192u +
                     (uint32_t)e * 64u + (uint32_t)j * 16u;
        cpa16(d, sp);
    };

#pragma unroll
    for (int r = 0; r < 5; r++) issueRawRow(0, r);
    issueW(0); cpa_commit();
#pragma unroll
    for (int r = 0; r < 5; r++) issueRawRow(1, r);
    issueW(1); cpa_commit();
    issueW(2); cpa_commit();

    const int lrow = lane & 15;
    const int lcol = (lane >> 4) * 16;

    for (int t = 0; t <= T; t++) {
        __syncthreads();
        if (t < T) {
            int b = t / 3, p = t - 3 * b;
            if (t >= 1 && t + 2 < T) issueW(t + 2);
            if (b + 2 < NBLK) {
                if (p == 0) { issueRawRow(b + 2, 0); issueRawRow(b + 2, 1); }
                else if (p == 1) { issueRawRow(b + 2, 2); issueRawRow(b + 2, 3); }
                else issueRawRow(b + 2, 4);
            }
            cpa_commit();
            asm volatile("cp.async.wait_group 3;");
        } else {
            asm volatile("cp.async.wait_group 0;");
        }
        __syncthreads();

        if (t < T) {  // convert stage t -> A slot t&1 (hi only)
            int b = t / 3, p = t - 3 * b;
            const char* rawB = smemc + (size_t)(b % 3) * RAWSZ;
            char* AH = smemc + AOFF + (size_t)(t & 1) * 8192;
#pragma unroll
            for (int kk = 0; kk < 2; kk++) {
                int u = tid + kk * 512;
                int e = u >> 3, cp = u & 7;
                const char* rb = rawB + e * 64 + cp * 8;
                float2 F0, F1;
                if (p == 0) {
                    float2 f0 = *(const float2*)(rb);
                    float2 f1 = *(const float2*)(rb + 8192);
                    float2 f3 = *(const float2*)(rb + 24576);
                    F0 = f0;
                    F1 = make_float2(f1.x + f3.x, f1.y + f3.y);
                } else if (p == 1) {
                    float2 f1 = *(const float2*)(rb + 8192);
                    float2 f2 = *(const float2*)(rb + 16384);
                    float2 f3 = *(const float2*)(rb + 24576);
                    float2 f4 = *(const float2*)(rb + 32768);
                    F0 = make_float2(f2.x + f4.x, f2.y + f4.y);
                    F1 = make_float2(fabsf(f1.x - f3.x), fabsf(f1.y - f3.y));
                } else {
                    float2 f1 = *(const float2*)(rb + 8192);
                    float2 f2 = *(const float2*)(rb + 16384);
                    float2 f3 = *(const float2*)(rb + 24576);
                    float2 f4 = *(const float2*)(rb + 32768);
                    F0 = make_float2(fabsf(f2.x - f4.x), fabsf(f2.y - f4.y));
                    float x1 = f1.x + f3.x, x2 = f2.x + f4.x, avg = 0.25f * (x1 + x2);
                    float d1 = f1.x - avg, d2 = f2.x - avg, d3 = f3.x - avg, d4 = f4.x - avg;
                    F1.x = d1 * d1 + d2 * d2 + d3 * d3 + d4 * d4;
                    x1 = f1.y + f3.y; x2 = f2.y + f4.y; avg = 0.25f * (x1 + x2);
                    d1 = f1.y - avg; d2 = f2.y - avg; d3 = f3.y - avg; d4 = f4.y - avg;
                    F1.y = d1 * d1 + d2 * d2 + d3 * d3 + d4 * d4;
                }
                __half2 h0v = __float22half2_rn(F0);
                __half2 h1v = __float22half2_rn(F1);
                *(uint32_t*)(AH + sw64((uint32_t)(e * 64 + cp * 4))) =
                    *reinterpret_cast<uint32_t*>(&h0v);
                *(uint32_t*)(AH + sw64((uint32_t)(e * 64 + 32 + cp * 4))) =
                    *reinterpret_cast<uint32_t*>(&h1v);
            }
        }
        if (t >= 1) {  // MMA stage t-1, single pass
            int st = t - 1;
            uint32_t AHs = sb + AOFF + (uint32_t)(st & 1) * 8192u;
            uint32_t Ws = sb + WOFF + (uint32_t)(st & 3) * 16384u;
#pragma unroll
            for (int ks = 0; ks < 2; ks++) {
                int ko = ks * 32;
                uint32_t ah[2][4], bb[4][4];
#pragma unroll
                for (int mi = 0; mi < 2; mi++)
                    ldsm4(ah[mi], AHs + sw64((wm * 32 + mi * 16 + lrow) * 64 + ko + lcol));
#pragma unroll
                for (int nj = 0; nj < 4; nj++)
                    ldsm4(bb[nj], Ws + sw64((wn * 64 + nj * 16 + lrow) * 64 + ko + lcol));
#pragma unroll
                for (int mi = 0; mi < 2; mi++)
#pragma unroll
                    for (int nj = 0; nj < 4; nj++) {
                        mma16816(acc[mi][2 * nj], ah[mi], bb[nj][0], bb[nj][2]);
                        mma16816(acc[mi][2 * nj + 1], ah[mi], bb[nj][1], bb[nj][3]);
                    }
            }
        }
    }

    // ---------------- epilogue ----------------
    __syncthreads();
    float* buf = (float*)smemc;                    // [256][129]
    float* bs = (float*)(smemc + 256 * 129 * 4);   // 512 floats
    {
        int q = lane >> 2, idq = lane & 3;
#pragma unroll
        for (int mi = 0; mi < 2; mi++)
#pragma unroll
            for (int p = 0; p < 8; p++) {
                int e = wm * 32 + mi * 16 + q;
                int o = wn * 64 + p * 8 + idq * 2;
                buf[o * 129 + e] = acc[mi][p][0];
                buf[(o + 1) * 129 + e] = acc[mi][p][1];
                buf[o * 129 + e + 8] = acc[mi][p][2];
                buf[(o + 1) * 129 + e + 8] = acc[mi][p][3];
            }
    }
    if (MODE == 0) bs[tid] = 0.f;
    __syncthreads();

    if (MODE == 0) {
        // e-major pass only: g_at = lrelu(h0), with fused BN stats
        int eo = tid >> 6, j = tid & 63;
        float s1[4] = {0.f, 0.f, 0.f, 0.f}, s2[4] = {0.f, 0.f, 0.f, 0.f};
#pragma unroll 1
        for (int it = 0; it < 16; it++) {
            int e = it * 8 + eo;
            float* dst = g_at + ((size_t)bCTA * EDGES + eCTA + e) * C1;
#pragma unroll
            for (int k = 0; k < 4; k++) {
                int o = j + 64 * k;
                float v = buf[o * 129 + e];
                float a = v > 0.f ? v : NEG * v;
                dst[o] = a;
                s1[k] += a;
                s2[k] += a * a;
            }
        }
#pragma unroll
        for (int k = 0; k < 4; k++) {
            atomicAdd(&bs[j + 64 * k], s1[k]);
            atomicAdd(&bs[256 + j + 64 * k], s2[k]);
        }
        __syncthreads();
        if (tid < 256) {
            atomicAdd(&g_sum1[tid], bs[tid]);
            atomicAdd(&g_sum2[tid], bs[tid + 256]);
        }
    } else {
        // residual add: h0 = inv_lrelu(g_at), accumulate into buf
        {
            int e = tid >> 2, j = tid & 3;
            const float* at_row = g_at + ((size_t)bCTA * EDGES + eCTA + e) * C1 + j * 64;
#pragma unroll 4
            for (int i = 0; i < 16; i++) {
                float4 av = *(const float4*)(at_row + 4 * i);
                float h0 = av.x > 0.f ? av.x : av.x * 100.f;
                float h1 = av.y > 0.f ? av.y : av.y * 100.f;
                float h2 = av.z > 0.f ? av.z : av.z * 100.f;
                float h3 = av.w > 0.f ? av.w : av.w * 100.f;
                int o = j * 64 + 4 * i;
                buf[(o + 0) * 129 + e] += h0;
                buf[(o + 1) * 129 + e] += h1;
                buf[(o + 2) * 129 + e] += h2;
                buf[(o + 3) * 129 + e] += h3;
            }
        }
        __syncthreads();
        int o = tid >> 1, hh = (tid & 1) * 64;
        float bo = g_bias[o];
        const float* srow = buf + o * 129 + hh;
        size_t gbase = ((size_t)bCTA * OUTC + o) * EDGES + eCTA + hh;
#pragma unroll 4
        for (int i = 0; i < 16; i++) {
            float v0 = srow[4 * i] + bo, v1 = srow[4 * i + 1] + bo;
            float v2 = srow[4 * i + 2] + bo, v3 = srow[4 * i + 3] + bo;
            v0 = v0 > 0.f ? v0 : NEG * v0;
            v1 = v1 > 0.f ? v1 : NEG * v1;
            v2 = v2 > 0.f ? v2 : NEG * v2;
            v3 = v3 > 0.f ? v3 : NEG * v3;
            *(float4*)(outp + gbase + 4 * i) = make_float4(v0, v1, v2, v3);
        }
    }
}

__global__ void bn_finalize(const float* __restrict__ gamma, const float* __restrict__ beta) {
    int o = threadIdx.x;
    float n = (float)((size_t)BATCH * EDGES);
    float mean = g_sum1[o] / n;
    float var = g_sum2[o] / n - mean * mean;
    float sc = gamma[o] * rsqrtf(var + BN_EPS_);
    g_scale[o] = sc;
    g_shift[o] = beta[o] - mean * sc;
}

extern "C" void kernel_launch(void* const* d_in, const int* in_sizes, int n_in,
                              void* d_out, int out_size) {
    (void)in_sizes; (void)n_in; (void)out_size;
    const float* x     = (const float*)d_in[0];
    const int*   gem   = (const int*)d_in[1];
    const float* W0    = (const float*)d_in[2];
    const float* W1    = (const float*)d_in[3];
    const float* gamma = (const float*)d_in[4];
    const float* beta  = (const float*)d_in[5];
    float* out = (float*)d_out;

    cudaFuncSetAttribute(gemm_fused<0>, cudaFuncAttributeMaxDynamicSharedMemorySize, FUSED_SMEM);
    cudaFuncSetAttribute(gemm_fused<1>, cudaFuncAttributeMaxDynamicSharedMemorySize, FUSED_SMEM);

    // 4th launch = gemm_fused<0> (ncu sample target)
    zero_sums<<<1, 256>>>();
    transpose_x<<<dim3(EDGES / 32, C0 / 32, BATCH), dim3(32, 8)>>>(x);
    prep_wh<0><<<(OUTC * 6 * C0 + 255) / 256, 256>>>(W0);
    gemm_fused<0><<<BATCH * EDGES / 128, 512, FUSED_SMEM>>>(nullptr, gem);

    bn_finalize<<<1, 256>>>(gamma, beta);
    prep_wh<1><<<(OUTC * 6 * C1 + 255) / 256, 256>>>(W1);
    bias_k<<<256, 256>>>(W1);

    gemm_fused<1><<<BATCH * EDGES / 128, 512, FUSED_SMEM>>>(out, gem);
}

// round 15
// speedup vs baseline: 1.8109x; 1.0363x over previous
#include <cuda_runtime.h>
#include <cuda_fp16.h>
#include <cstdint>

#define BATCH 8
#define EDGES 16384
#define C0 128
#define C1 256
#define OUTC 256
#define NEG 0.01f
#define BN_EPS_ 1e-5f

__device__ __half g_W0h[OUTC * 6 * C0];
__device__ __half g_W1h[OUTC * 6 * C1];   // BN-folded
__device__ float g_xt[(size_t)BATCH * EDGES * C0];
__device__ float g_at[(size_t)BATCH * EDGES * C1];   // lrelu(h0), pre-BN, E-major
__device__ float g_sum1[OUTC], g_sum2[OUTC], g_scale[OUTC], g_shift[OUTC], g_bias[OUTC];

__device__ __forceinline__ uint32_t smem_u32(const void* p) {
    uint32_t a;
    asm("{ .reg .u64 t; cvta.to.shared.u64 t, %1; cvt.u32.u64 %0, t; }" : "=r"(a) : "l"(p));
    return a;
}
__device__ __forceinline__ uint32_t sw64(uint32_t x) { return x ^ ((x >> 3) & 0x30); }
__device__ __forceinline__ void cpa16(uint32_t s, const void* g) {
    asm volatile("cp.async.cg.shared.global [%0], [%1], 16;" :: "r"(s), "l"(g));
}
__device__ __forceinline__ void cpa_commit() { asm volatile("cp.async.commit_group;"); }
__device__ __forceinline__ void ldsm4(uint32_t* r, uint32_t addr) {
    asm volatile("ldmatrix.sync.aligned.m8n8.x4.shared.b16 {%0,%1,%2,%3}, [%4];"
                 : "=r"(r[0]), "=r"(r[1]), "=r"(r[2]), "=r"(r[3]) : "r"(addr));
}
__device__ __forceinline__ void mma16816(float* d, const uint32_t* a, uint32_t b0, uint32_t b1) {
    asm volatile(
        "mma.sync.aligned.m16n8k16.row.col.f32.f16.f16.f32 "
        "{%0,%1,%2,%3}, {%4,%5,%6,%7}, {%8,%9}, {%0,%1,%2,%3};"
        : "+f"(d[0]), "+f"(d[1]), "+f"(d[2]), "+f"(d[3])
        : "r"(a[0]), "r"(a[1]), "r"(a[2]), "r"(a[3]), "r"(b0), "r"(b1));
}
__device__ __forceinline__ uint32_t pack_h2(float2 v) {
    __half2 h = __float22half2_rn(v);
    return *reinterpret_cast<uint32_t*>(&h);
}

__global__ void zero_sums() {
    g_sum1[threadIdx.x] = 0.f;
    g_sum2[threadIdx.x] = 0.f;
}

// K-order: kp = 96b+32p+q; c = 16b+(q&15); jp = 2p+(q>>4); jp: f0,x1,x2,x3,x4,x6
template <int MODE>
__global__ void prep_wh(const float* __restrict__ W) {
    constexpr int C = MODE ? C1 : C0;
    constexpr int K = 6 * C;
    __half* Wh = MODE ? g_W1h : g_W0h;
    int i = blockIdx.x * blockDim.x + threadIdx.x;
    if (i < OUTC * K) {
        int kp = i % K, o = i / K;
        int b = kp / 96, rem = kp % 96;
        int p = rem >> 5, q = rem & 31;
        int c = 16 * b + (q & 15);
        int jp = 2 * p + (q >> 4);
        int jorig = (jp == 5) ? 6 : jp;
        const float* wr = W + (size_t)o * (7 * C) + c * 7;
        float v = wr[jorig];
        if (jp == 1 || jp == 2) v += wr[5];
        if (MODE) {
            float s = g_scale[c];
            v *= (jp <= 2) ? s : ((jp <= 4) ? fabsf(s) : s * s);
        }
        Wh[(size_t)o * K + kp] = __float2half(v);
    }
}

__global__ void bias_k(const float* __restrict__ W1) {
    int o = blockIdx.x, c = threadIdx.x;
    const float* w = W1 + (size_t)o * (7 * C1) + c * 7;
    __shared__ float red[256];
    red[c] = g_shift[c] * (w[0] + 2.f * (w[1] + w[2]) + 4.f * w[5]);
    __syncthreads();
    for (int s = 128; s; s >>= 1) {
        if (c < s) red[c] += red[c + s];
        __syncthreads();
    }
    if (c == 0) g_bias[o] = red[0];
}

__global__ void transpose_x(const float* __restrict__ x) {
    __shared__ float tile[32][33];
    int b = blockIdx.z, e0 = blockIdx.x * 32, c0 = blockIdx.y * 32;
    int tx = threadIdx.x, ty = threadIdx.y;
#pragma unroll
    for (int i = 0; i < 32; i += 8)
        tile[ty + i][tx] = x[((size_t)b * C0 + (c0 + ty + i)) * EDGES + e0 + tx];
    __syncthreads();
#pragma unroll
    for (int i = 0; i < 32; i += 8)
        g_xt[((size_t)b * EDGES + (e0 + ty + i)) * C0 + c0 + tx] = tile[tx][ty + i];
}

// smem: RAW 3x40960 @0 | A 4x8192 @122880 | W 4x16384 @155648 | gemS @221184
#define RAWSZ 40960u
#define AOFF 122880u
#define WOFF 155648u
#define GEMOFF 221184u
#define FUSED_SMEM 223232

template <int MODE>
__global__ __launch_bounds__(256, 1) void gemm_fused(float* __restrict__ outp,
                                                     const int* __restrict__ gem) {
    constexpr int C = MODE ? C1 : C0;
    constexpr int NBLK = C / 16;
    constexpr int T = 3 * NBLK;
    constexpr int K = 6 * C;
    const float* __restrict__ src = MODE ? g_at : g_xt;
    const __half* __restrict__ Wh = MODE ? g_W1h : g_W0h;

    extern __shared__ __align__(1024) char smemc[];
    uint32_t sb = smem_u32(smemc);
    const int tid = threadIdx.x, wid = tid >> 5, lane = tid & 31;
    const int wm = wid & 1, wn = wid >> 1;     // 2 M-groups x 4 N-groups, 64x64 tiles
    const int eCTA = (blockIdx.x & 127) * 128;
    const int bCTA = blockIdx.x >> 7;
    const float* __restrict__ srcB = src + (size_t)bCTA * EDGES * C;

    int* gemS = (int*)(smemc + GEMOFF);
    {
        size_t gbase = ((size_t)bCTA * EDGES + eCTA) * 4;
        gemS[tid] = gem[gbase + tid];
        gemS[tid + 256] = gem[gbase + 256 + tid];
    }
    __syncthreads();

    float acc[4][8][4];
#pragma unroll
    for (int i = 0; i < 4; i++)
#pragma unroll
        for (int j = 0; j < 8; j++)
#pragma unroll
            for (int k = 0; k < 4; k++) acc[i][j][k] = 0.f;

    const int lrW = tid >> 2, lcW = tid & 3;
    auto issueW = [&](int k) {
        uint32_t wd = sb + WOFF + (uint32_t)(k & 3) * 16384u;
        const __half* ws = Wh + k * 32 + lcW * 8;
#pragma unroll
        for (int i = 0; i < 4; i++) {
            int r = lrW + i * 64;
            cpa16(wd + sw64(r * 64 + lcW * 16), ws + (size_t)r * K);
        }
    };
    auto issueRawRow = [&](int blk, int r) {
        int e = tid >> 1, j0 = (tid & 1) * 2;
        int rid = (r == 0) ? (eCTA + e) : gemS[e * 4 + (r - 1)];
        const float* sp = srcB + (size_t)rid * C + blk * 16;
        uint32_t d = sb + (uint32_t)(blk % 3) * RAWSZ + (uint32_t)r * 8192u + (uint32_t)e * 64u;
        cpa16(d + j0 * 16u, sp + j0 * 4);
        cpa16(d + j0 * 16u + 16u, sp + j0 * 4 + 4);
    };

#pragma unroll
    for (int r = 0; r < 5; r++) issueRawRow(0, r);
    issueW(0); cpa_commit();
#pragma unroll
    for (int r = 0; r < 5; r++) issueRawRow(1, r);
    issueW(1); cpa_commit();
    issueW(2); cpa_commit();

    const int lrow = lane & 15;
    const int lcol = (lane >> 4) * 16;

    for (int t = 0; t <= T; t++) {
        __syncthreads();
        if (t < T) {
            int b = t / 3, p = t - 3 * b;
            if (t >= 1 && t + 2 < T) issueW(t + 2);
            if (b + 2 < NBLK) {
                if (p == 0) { issueRawRow(b + 2, 0); issueRawRow(b + 2, 1); }
                else if (p == 1) { issueRawRow(b + 2, 2); issueRawRow(b + 2, 3); }
                else issueRawRow(b + 2, 4);
            }
            cpa_commit();
            asm volatile("cp.async.wait_group 3;");
        } else {
            asm volatile("cp.async.wait_group 0;");
        }
        __syncthreads();

        if (t < T && (t % 3) == 0) {
            // convert whole raw block b -> A slots t, t+1, t+2 (all 6 features, one read)
            int b = t / 3;
            const char* rawB = smemc + (size_t)(b % 3) * RAWSZ;
            char* A0 = smemc + AOFF + (size_t)(t & 3) * 8192;
            char* A1 = smemc + AOFF + (size_t)((t + 1) & 3) * 8192;
            char* A2 = smemc + AOFF + (size_t)((t + 2) & 3) * 8192;
#pragma unroll
            for (int u = 0; u < 4; u++) {
                int unit = tid + u * 256;
                int e = unit >> 3, cp = unit & 7;
                const char* rb = rawB + e * 64 + cp * 8;
                float2 f0 = *(const float2*)(rb);
                float2 f1 = *(const float2*)(rb + 8192);
                float2 f2 = *(const float2*)(rb + 16384);
                float2 f3 = *(const float2*)(rb + 24576);
                float2 f4 = *(const float2*)(rb + 32768);
                float2 x1 = make_float2(f1.x + f3.x, f1.y + f3.y);
                float2 x2 = make_float2(f2.x + f4.x, f2.y + f4.y);
                float2 x3 = make_float2(fabsf(f1.x - f3.x), fabsf(f1.y - f3.y));
                float2 x4 = make_float2(fabsf(f2.x - f4.x), fabsf(f2.y - f4.y));
                float2 x6;
                {
                    float avg = 0.25f * (x1.x + x2.x);
                    float d1 = f1.x - avg, d2 = f2.x - avg, d3 = f3.x - avg, d4 = f4.x - avg;
                    x6.x = d1 * d1 + d2 * d2 + d3 * d3 + d4 * d4;
                    avg = 0.25f * (x1.y + x2.y);
                    d1 = f1.y - avg; d2 = f2.y - avg; d3 = f3.y - avg; d4 = f4.y - avg;
                    x6.y = d1 * d1 + d2 * d2 + d3 * d3 + d4 * d4;
                }
                uint32_t off0 = sw64((uint32_t)(e * 64 + cp * 4));
                uint32_t off1 = sw64((uint32_t)(e * 64 + 32 + cp * 4));
                *(uint32_t*)(A0 + off0) = pack_h2(f0);
                *(uint32_t*)(A0 + off1) = pack_h2(x1);
                *(uint32_t*)(A1 + off0) = pack_h2(x2);
                *(uint32_t*)(A1 + off1) = pack_h2(x3);
                *(uint32_t*)(A2 + off0) = pack_h2(x4);
                *(uint32_t*)(A2 + off1) = pack_h2(x6);
            }
        }
        if (t >= 1) {  // MMA stage t-1, 64x64 warp tile
            int st = t - 1;
            uint32_t AHs = sb + AOFF + (uint32_t)(st & 3) * 8192u;
            uint32_t Ws = sb + WOFF + (uint32_t)(st & 3) * 16384u;
#pragma unroll
            for (int ks = 0; ks < 2; ks++) {
                int ko = ks * 32;
                uint32_t ah[4][4], bb[4][4];
#pragma unroll
                for (int mi = 0; mi < 4; mi++)
                    ldsm4(ah[mi], AHs + sw64((wm * 64 + mi * 16 + lrow) * 64 + ko + lcol));
#pragma unroll
                for (int nj = 0; nj < 4; nj++)
                    ldsm4(bb[nj], Ws + sw64((wn * 64 + nj * 16 + lrow) * 64 + ko + lcol));
#pragma unroll
                for (int mi = 0; mi < 4; mi++)
#pragma unroll
                    for (int nj = 0; nj < 4; nj++) {
                        mma16816(acc[mi][2 * nj], ah[mi], bb[nj][0], bb[nj][2]);
                        mma16816(acc[mi][2 * nj + 1], ah[mi], bb[nj][1], bb[nj][3]);
                    }
            }
        }
    }

    // ---------------- epilogue ----------------
    __syncthreads();
    float* buf = (float*)smemc;                    // [256][129]
    float* bs = (float*)(smemc + 256 * 129 * 4);   // 512 floats
    {
        int q = lane >> 2, idq = lane & 3;
#pragma unroll
        for (int mi = 0; mi < 4; mi++)
#pragma unroll
            for (int p = 0; p < 8; p++) {
                int e = wm * 64 + mi * 16 + q;
                int o = wn * 64 + p * 8 + idq * 2;
                buf[o * 129 + e] = acc[mi][p][0];
                buf[(o + 1) * 129 + e] = acc[mi][p][1];
                buf[o * 129 + e + 8] = acc[mi][p][2];
                buf[(o + 1) * 129 + e + 8] = acc[mi][p][3];
            }
    }
    if (MODE == 0) { bs[tid] = 0.f; bs[tid + 256] = 0.f; }
    __syncthreads();

    if (MODE == 0) {
        // e-major pass: g_at = lrelu(h0), fused BN stats
        int eo = tid >> 5, j = tid & 31;
        float s1[8], s2[8];
#pragma unroll
        for (int k = 0; k < 8; k++) { s1[k] = 0.f; s2[k] = 0.f; }
#pragma unroll 1
        for (int it = 0; it < 16; it++) {
            int e = it * 8 + eo;
            float* dst = g_at + ((size_t)bCTA * EDGES + eCTA + e) * C1;
#pragma unroll
            for (int k = 0; k < 8; k++) {
                int o = j + 32 * k;
                float v = buf[o * 129 + e];
                float a = v > 0.f ? v : NEG * v;
                dst[o] = a;
                s1[k] += a;
                s2[k] += a * a;
            }
        }
#pragma unroll
        for (int k = 0; k < 8; k++) {
            atomicAdd(&bs[j + 32 * k], s1[k]);
            atomicAdd(&bs[256 + j + 32 * k], s2[k]);
        }
        __syncthreads();
        atomicAdd(&g_sum1[tid], bs[tid]);
        atomicAdd(&g_sum2[tid], bs[tid + 256]);
    } else {
        // residual add: h0 = inv_lrelu(g_at), accumulate into buf
        {
            int e = tid >> 1, j = tid & 1;
            const float* at_row = g_at + ((size_t)bCTA * EDGES + eCTA + e) * C1 + j * 128;
#pragma unroll 4
            for (int i = 0; i < 32; i++) {
                float4 av = *(const float4*)(at_row + 4 * i);
                float h0 = av.x > 0.f ? av.x : av.x * 100.f;
                float h1 = av.y > 0.f ? av.y : av.y * 100.f;
                float h2 = av.z > 0.f ? av.z : av.z * 100.f;
                float h3 = av.w > 0.f ? av.w : av.w * 100.f;
                int o = j * 128 + 4 * i;
                buf[(o + 0) * 129 + e] += h0;
                buf[(o + 1) * 129 + e] += h1;
                buf[(o + 2) * 129 + e] += h2;
                buf[(o + 3) * 129 + e] += h3;
            }
        }
        __syncthreads();
        int o = tid;
        float bo = g_bias[o];
        const float* srow = buf + o * 129;
        size_t gbase = ((size_t)bCTA * OUTC + o) * EDGES + eCTA;
#pragma unroll 4
        for (int i = 0; i < 32; i++) {
            float v0 = srow[4 * i] + bo, v1 = srow[4 * i + 1] + bo;
            float v2 = srow[4 * i + 2] + bo, v3 = srow[4 * i + 3] + bo;
            v0 = v0 > 0.f ? v0 : NEG * v0;
            v1 = v1 > 0.f ? v1 : NEG * v1;
            v2 = v2 > 0.f ? v2 : NEG * v2;
            v3 = v3 > 0.f ? v3 : NEG * v3;
            *(float4*)(outp + gbase + 4 * i) = make_float4(v0, v1, v2, v3);
        }
    }
}

__global__ void bn_finalize(const float* __restrict__ gamma, const float* __restrict__ beta) {
    int o = threadIdx.x;
    float n = (float)((size_t)BATCH * EDGES);
    float mean = g_sum1[o] / n;
    float var = g_sum2[o] / n - mean * mean;
    float sc = gamma[o] * rsqrtf(var + BN_EPS_);
    g_scale[o] = sc;
    g_shift[o] = beta[o] - mean * sc;
}

extern "C" void kernel_launch(void* const* d_in, const int* in_sizes, int n_in,
                              void* d_out, int out_size) {
    (void)in_sizes; (void)n_in; (void)out_size;
    const float* x     = (const float*)d_in[0];
    const int*   gem   = (const int*)d_in[1];
    const float* W0    = (const float*)d_in[2];
    const float* W1    = (const float*)d_in[3];
    const float* gamma = (const float*)d_in[4];
    const float* beta  = (const float*)d_in[5];
    float* out = (float*)d_out;

    cudaFuncSetAttribute(gemm_fused<0>, cudaFuncAttributeMaxDynamicSharedMemorySize, FUSED_SMEM);
    cudaFuncSetAttribute(gemm_fused<1>, cudaFuncAttributeMaxDynamicSharedMemorySize, FUSED_SMEM);

    // 4th launch = gemm_fused<0> (ncu sample target)
    zero_sums<<<1, 256>>>();
    transpose_x<<<dim3(EDGES / 32, C0 / 32, BATCH), dim3(32, 8)>>>(x);
    prep_wh<0><<<(OUTC * 6 * C0 + 255) / 256, 256>>>(W0);
    gemm_fused<0><<<BATCH * EDGES / 128, 256, FUSED_SMEM>>>(nullptr, gem);

    bn_finalize<<<1, 256>>>(gamma, beta);
    prep_wh<1><<<(OUTC * 6 * C1 + 255) / 256, 256>>>(W1);
    bias_k<<<256, 256>>>(W1);

    gemm_fused<1><<<BATCH * EDGES / 128, 256, FUSED_SMEM>>>(out, gem);
}

// round 16
// speedup vs baseline: 1.8981x; 1.0482x over previous
#include <cuda_runtime.h>
#include <cuda_fp16.h>
#include <cstdint>

#define BATCH 8
#define EDGES 16384
#define C0 128
#define C1 256
#define OUTC 256
#define NEG 0.01f
#define BN_EPS_ 1e-5f

__device__ __half g_W0h[OUTC * 6 * C0];
__device__ __half g_W1h[OUTC * 6 * C1];   // BN-folded
__device__ float g_xt[(size_t)BATCH * EDGES * C0];
__device__ float g_at[(size_t)BATCH * EDGES * C1];   // lrelu(h0), pre-BN, E-major
__device__ float g_sum1[OUTC], g_sum2[OUTC], g_scale[OUTC], g_shift[OUTC], g_bias[OUTC];

__device__ __forceinline__ uint32_t smem_u32(const void* p) {
    uint32_t a;
    asm("{ .reg .u64 t; cvta.to.shared.u64 t, %1; cvt.u32.u64 %0, t; }" : "=r"(a) : "l"(p));
    return a;
}
__device__ __forceinline__ uint32_t sw64(uint32_t x) { return x ^ ((x >> 3) & 0x30); }
__device__ __forceinline__ void cpa16(uint32_t s, const void* g) {
    asm volatile("cp.async.cg.shared.global [%0], [%1], 16;" :: "r"(s), "l"(g));
}
__device__ __forceinline__ void cpa_commit() { asm volatile("cp.async.commit_group;"); }
__device__ __forceinline__ void ldsm4(uint32_t* r, uint32_t addr) {
    asm volatile("ldmatrix.sync.aligned.m8n8.x4.shared.b16 {%0,%1,%2,%3}, [%4];"
                 : "=r"(r[0]), "=r"(r[1]), "=r"(r[2]), "=r"(r[3]) : "r"(addr));
}
__device__ __forceinline__ void mma16816(float* d, const uint32_t* a, uint32_t b0, uint32_t b1) {
    asm volatile(
        "mma.sync.aligned.m16n8k16.row.col.f32.f16.f16.f32 "
        "{%0,%1,%2,%3}, {%4,%5,%6,%7}, {%8,%9}, {%0,%1,%2,%3};"
        : "+f"(d[0]), "+f"(d[1]), "+f"(d[2]), "+f"(d[3])
        : "r"(a[0]), "r"(a[1]), "r"(a[2]), "r"(a[3]), "r"(b0), "r"(b1));
}
__device__ __forceinline__ uint32_t pack_h2(float2 v) {
    __half2 h = __float22half2_rn(v);
    return *reinterpret_cast<uint32_t*>(&h);
}

__global__ void zero_sums() {
    g_sum1[threadIdx.x] = 0.f;
    g_sum2[threadIdx.x] = 0.f;
}

// K-order: kp = 96b+32p+q; c = 16b+(q&15); jp = 2p+(q>>4); jp: f0,x1,x2,x3,x4,x6
template <int MODE>
__global__ void prep_wh(const float* __restrict__ W) {
    constexpr int C = MODE ? C1 : C0;
    constexpr int K = 6 * C;
    __half* Wh = MODE ? g_W1h : g_W0h;
    int i = blockIdx.x * blockDim.x + threadIdx.x;
    if (i < OUTC * K) {
        int kp = i % K, o = i / K;
        int b = kp / 96, rem = kp % 96;
        int p = rem >> 5, q = rem & 31;
        int c = 16 * b + (q & 15);
        int jp = 2 * p + (q >> 4);
        int jorig = (jp == 5) ? 6 : jp;
        const float* wr = W + (size_t)o * (7 * C) + c * 7;
        float v = wr[jorig];
        if (jp == 1 || jp == 2) v += wr[5];
        if (MODE) {
            float s = g_scale[c];
            v *= (jp <= 2) ? s : ((jp <= 4) ? fabsf(s) : s * s);
        }
        Wh[(size_t)o * K + kp] = __float2half(v);
    }
}

__global__ void bias_k(const float* __restrict__ W1) {
    int o = blockIdx.x, c = threadIdx.x;
    const float* w = W1 + (size_t)o * (7 * C1) + c * 7;
    __shared__ float red[256];
    red[c] = g_shift[c] * (w[0] + 2.f * (w[1] + w[2]) + 4.f * w[5]);
    __syncthreads();
    for (int s = 128; s; s >>= 1) {
        if (c < s) red[c] += red[c + s];
        __syncthreads();
    }
    if (c == 0) g_bias[o] = red[0];
}

__global__ void transpose_x(const float* __restrict__ x) {
    __shared__ float tile[32][33];
    int b = blockIdx.z, e0 = blockIdx.x * 32, c0 = blockIdx.y * 32;
    int tx = threadIdx.x, ty = threadIdx.y;
#pragma unroll
    for (int i = 0; i < 32; i += 8)
        tile[ty + i][tx] = x[((size_t)b * C0 + (c0 + ty + i)) * EDGES + e0 + tx];
    __syncthreads();
#pragma unroll
    for (int i = 0; i < 32; i += 8)
        g_xt[((size_t)b * EDGES + (e0 + ty + i)) * C0 + c0 + tx] = tile[tx][ty + i];
}

// smem: RAW 3x40960 @0 | A 4x8192 @122880 | W 4x16384 @155648 | gemS @221184
#define RAWSZ 40960u
#define AOFF 122880u
#define WOFF 155648u
#define GEMOFF 221184u
#define FUSED_SMEM 223232

template <int MODE>
__global__ __launch_bounds__(512, 1) void gemm_fused(float* __restrict__ outp,
                                                     const int* __restrict__ gem) {
    constexpr int C = MODE ? C1 : C0;
    constexpr int NBLK = C / 16;
    constexpr int T = 3 * NBLK;
    constexpr int K = 6 * C;
    const float* __restrict__ src = MODE ? g_at : g_xt;
    const __half* __restrict__ Wh = MODE ? g_W1h : g_W0h;

    extern __shared__ __align__(1024) char smemc[];
    uint32_t sb = smem_u32(smemc);
    const int tid = threadIdx.x, wid = tid >> 5, lane = tid & 31;
    const int wm = wid & 3, wn = wid >> 2;   // 4 M-groups x 4 N-groups, 32x64 tiles
    const int eCTA = (blockIdx.x & 127) * 128;
    const int bCTA = blockIdx.x >> 7;
    const float* __restrict__ srcB = src + (size_t)bCTA * EDGES * C;

    int* gemS = (int*)(smemc + GEMOFF);
    gemS[tid] = gem[((size_t)bCTA * EDGES + eCTA) * 4 + tid];
    __syncthreads();

    float acc[2][8][4];
#pragma unroll
    for (int i = 0; i < 2; i++)
#pragma unroll
        for (int j = 0; j < 8; j++)
#pragma unroll
            for (int k = 0; k < 4; k++) acc[i][j][k] = 0.f;

    const int lrW = tid >> 2, lcW = tid & 3;
    auto issueW = [&](int k) {
        uint32_t wd = sb + WOFF + (uint32_t)(k & 3) * 16384u;
        const __half* ws = Wh + k * 32 + (size_t)lrW * K + lcW * 8;
        cpa16(wd + sw64(lrW * 64 + lcW * 16), ws);
        cpa16(wd + sw64((lrW + 128) * 64 + lcW * 16), ws + (size_t)128 * K);
    };
    auto issueRawRow = [&](int blk, int r) {
        int e = tid >> 2, j = tid & 3;
        int rid = (r == 0) ? (eCTA + e) : gemS[e * 4 + (r - 1)];
        const float* sp = srcB + (size_t)rid * C + blk * 16 + j * 4;
        uint32_t d = sb + (uint32_t)(blk % 3) * RAWSZ + (uint32_t)r * 8192u +
                     (uint32_t)e * 64u + (uint32_t)j * 16u;
        cpa16(d, sp);
    };

#pragma unroll
    for (int r = 0; r < 5; r++) issueRawRow(0, r);
    issueW(0); cpa_commit();
#pragma unroll
    for (int r = 0; r < 5; r++) issueRawRow(1, r);
    issueW(1); cpa_commit();
    issueW(2); cpa_commit();

    const int lrow = lane & 15;
    const int lcol = (lane >> 4) * 16;

    for (int t = 0; t <= T; t++) {
        __syncthreads();
        if (t < T) {
            int b = t / 3, p = t - 3 * b;
            if (t >= 1 && t + 2 < T) issueW(t + 2);
            if (b + 2 < NBLK) {
                if (p == 0) { issueRawRow(b + 2, 0); issueRawRow(b + 2, 1); }
                else if (p == 1) { issueRawRow(b + 2, 2); issueRawRow(b + 2, 3); }
                else issueRawRow(b + 2, 4);
            }
            cpa_commit();
            asm volatile("cp.async.wait_group 3;");
        } else {
            asm volatile("cp.async.wait_group 0;");
        }
        __syncthreads();

        if (t < T && (t % 3) == 0) {
            // convert whole raw block -> A slots t, t+1, t+2 (read f0..f4 once)
            int b = t / 3;
            const char* rawB = smemc + (size_t)(b % 3) * RAWSZ;
            char* A0 = smemc + AOFF + (size_t)(t & 3) * 8192;
            char* A1 = smemc + AOFF + (size_t)((t + 1) & 3) * 8192;
            char* A2 = smemc + AOFF + (size_t)((t + 2) & 3) * 8192;
#pragma unroll
            for (int u = 0; u < 2; u++) {
                int unit = tid + u * 512;
                int e = unit >> 3, cp = unit & 7;
                const char* rb = rawB + e * 64 + cp * 8;
                float2 f0 = *(const float2*)(rb);
                float2 f1 = *(const float2*)(rb + 8192);
                float2 f2 = *(const float2*)(rb + 16384);
                float2 f3 = *(const float2*)(rb + 24576);
                float2 f4 = *(const float2*)(rb + 32768);
                float2 x1 = make_float2(f1.x + f3.x, f1.y + f3.y);
                float2 x2 = make_float2(f2.x + f4.x, f2.y + f4.y);
                float2 x3 = make_float2(fabsf(f1.x - f3.x), fabsf(f1.y - f3.y));
                float2 x4 = make_float2(fabsf(f2.x - f4.x), fabsf(f2.y - f4.y));
                float2 x6;
                {
                    float avg = 0.25f * (x1.x + x2.x);
                    float d1 = f1.x - avg, d2 = f2.x - avg, d3 = f3.x - avg, d4 = f4.x - avg;
                    x6.x = d1 * d1 + d2 * d2 + d3 * d3 + d4 * d4;
                    avg = 0.25f * (x1.y + x2.y);
                    d1 = f1.y - avg; d2 = f2.y - avg; d3 = f3.y - avg; d4 = f4.y - avg;
                    x6.y = d1 * d1 + d2 * d2 + d3 * d3 + d4 * d4;
                }
                uint32_t off0 = sw64((uint32_t)(e * 64 + cp * 4));
                uint32_t off1 = sw64((uint32_t)(e * 64 + 32 + cp * 4));
                *(uint32_t*)(A0 + off0) = pack_h2(f0);
                *(uint32_t*)(A0 + off1) = pack_h2(x1);
                *(uint32_t*)(A1 + off0) = pack_h2(x2);
                *(uint32_t*)(A1 + off1) = pack_h2(x3);
                *(uint32_t*)(A2 + off0) = pack_h2(x4);
                *(uint32_t*)(A2 + off1) = pack_h2(x6);
            }
        }
        if (t >= 1) {  // MMA stage t-1, 32x64 warp tile
            int st = t - 1;
            uint32_t AHs = sb + AOFF + (uint32_t)(st & 3) * 8192u;
            uint32_t Ws = sb + WOFF + (uint32_t)(st & 3) * 16384u;
#pragma unroll
            for (int ks = 0; ks < 2; ks++) {
                int ko = ks * 32;
                uint32_t ah[2][4], bb[4][4];
#pragma unroll
                for (int mi = 0; mi < 2; mi++)
                    ldsm4(ah[mi], AHs + sw64((wm * 32 + mi * 16 + lrow) * 64 + ko + lcol));
#pragma unroll
                for (int nj = 0; nj < 4; nj++)
                    ldsm4(bb[nj], Ws + sw64((wn * 64 + nj * 16 + lrow) * 64 + ko + lcol));
#pragma unroll
                for (int mi = 0; mi < 2; mi++)
#pragma unroll
                    for (int nj = 0; nj < 4; nj++) {
                        mma16816(acc[mi][2 * nj], ah[mi], bb[nj][0], bb[nj][2]);
                        mma16816(acc[mi][2 * nj + 1], ah[mi], bb[nj][1], bb[nj][3]);
                    }
            }
        }
    }

    // ---------------- epilogue ----------------
    __syncthreads();
    float* buf = (float*)smemc;                    // [256][129]
    float* bs = (float*)(smemc + 256 * 129 * 4);   // 512 floats
    {
        int q = lane >> 2, idq = lane & 3;
#pragma unroll
        for (int mi = 0; mi < 2; mi++)
#pragma unroll
            for (int p = 0; p < 8; p++) {
                int e = wm * 32 + mi * 16 + q;
                int o = wn * 64 + p * 8 + idq * 2;
                buf[o * 129 + e] = acc[mi][p][0];
                buf[(o + 1) * 129 + e] = acc[mi][p][1];
                buf[o * 129 + e + 8] = acc[mi][p][2];
                buf[(o + 1) * 129 + e + 8] = acc[mi][p][3];
            }
    }
    if (MODE == 0) bs[tid] = 0.f;
    __syncthreads();

    if (MODE == 0) {
        // e-major pass: g_at = lrelu(h0), fused BN stats
        int eo = tid >> 6, j = tid & 63;
        float s1[4] = {0.f, 0.f, 0.f, 0.f}, s2[4] = {0.f, 0.f, 0.f, 0.f};
#pragma unroll 1
        for (int it = 0; it < 16; it++) {
            int e = it * 8 + eo;
            float* dst = g_at + ((size_t)bCTA * EDGES + eCTA + e) * C1;
#pragma unroll
            for (int k = 0; k < 4; k++) {
                int o = j + 64 * k;
                float v = buf[o * 129 + e];
                float a = v > 0.f ? v : NEG * v;
                dst[o] = a;
                s1[k] += a;
                s2[k] += a * a;
            }
        }
#pragma unroll
        for (int k = 0; k < 4; k++) {
            atomicAdd(&bs[j + 64 * k], s1[k]);
            atomicAdd(&bs[256 + j + 64 * k], s2[k]);
        }
        __syncthreads();
        if (tid < 256) {
            atomicAdd(&g_sum1[tid], bs[tid]);
            atomicAdd(&g_sum2[tid], bs[tid + 256]);
        }
    } else {
        // residual add: h0 = inv_lrelu(g_at), accumulate into buf
        {
            int e = tid >> 2, j = tid & 3;
            const float* at_row = g_at + ((size_t)bCTA * EDGES + eCTA + e) * C1 + j * 64;
#pragma unroll 4
            for (int i = 0; i < 16; i++) {
                float4 av = *(const float4*)(at_row + 4 * i);
                float h0 = av.x > 0.f ? av.x : av.x * 100.f;
                float h1 = av.y > 0.f ? av.y : av.y * 100.f;
                float h2 = av.z > 0.f ? av.z : av.z * 100.f;
                float h3 = av.w > 0.f ? av.w : av.w * 100.f;
                int o = j * 64 + 4 * i;
                buf[(o + 0) * 129 + e] += h0;
                buf[(o + 1) * 129 + e] += h1;
                buf[(o + 2) * 129 + e] += h2;
                buf[(o + 3) * 129 + e] += h3;
            }
        }
        __syncthreads();
        int o = tid >> 1, hh = (tid & 1) * 64;
        float bo = g_bias[o];
        const float* srow = buf + o * 129 + hh;
        size_t gbase = ((size_t)bCTA * OUTC + o) * EDGES + eCTA + hh;
#pragma unroll 4
        for (int i = 0; i < 16; i++) {
            float v0 = srow[4 * i] + bo, v1 = srow[4 * i + 1] + bo;
            float v2 = srow[4 * i + 2] + bo, v3 = srow[4 * i + 3] + bo;
            v0 = v0 > 0.f ? v0 : NEG * v0;
            v1 = v1 > 0.f ? v1 : NEG * v1;
            v2 = v2 > 0.f ? v2 : NEG * v2;
            v3 = v3 > 0.f ? v3 : NEG * v3;
            *(float4*)(outp + gbase + 4 * i) = make_float4(v0, v1, v2, v3);
        }
    }
}

__global__ void bn_finalize(const float* __restrict__ gamma, const float* __restrict__ beta) {
    int o = threadIdx.x;
    float n = (float)((size_t)BATCH * EDGES);
    float mean = g_sum1[o] / n;
    float var = g_sum2[o] / n - mean * mean;
    float sc = gamma[o] * rsqrtf(var + BN_EPS_);
    g_scale[o] = sc;
    g_shift[o] = beta[o] - mean * sc;
}

extern "C" void kernel_launch(void* const* d_in, const int* in_sizes, int n_in,
                              void* d_out, int out_size) {
    (void)in_sizes; (void)n_in; (void)out_size;
    const float* x     = (const float*)d_in[0];
    const int*   gem   = (const int*)d_in[1];
    const float* W0    = (const float*)d_in[2];
    const float* W1    = (const float*)d_in[3];
    const float* gamma = (const float*)d_in[4];
    const float* beta  = (const float*)d_in[5];
    float* out = (float*)d_out;

    cudaFuncSetAttribute(gemm_fused<0>, cudaFuncAttributeMaxDynamicSharedMemorySize, FUSED_SMEM);
    cudaFuncSetAttribute(gemm_fused<1>, cudaFuncAttributeMaxDynamicSharedMemorySize, FUSED_SMEM);

    // 4th launch = gemm_fused<0> (ncu sample target)
    zero_sums<<<1, 256>>>();
    transpose_x<<<dim3(EDGES / 32, C0 / 32, BATCH), dim3(32, 8)>>>(x);
    prep_wh<0><<<(OUTC * 6 * C0 + 255) / 256, 256>>>(W0);
    gemm_fused<0><<<BATCH * EDGES / 128, 512, FUSED_SMEM>>>(nullptr, gem);

    bn_finalize<<<1, 256>>>(gamma, beta);
    prep_wh<1><<<(OUTC * 6 * C1 + 255) / 256, 256>>>(W1);
    bias_k<<<256, 256>>>(W1);

    gemm_fused<1><<<BATCH * EDGES / 128, 512, FUSED_SMEM>>>(out, gem);
}